// round 1
// baseline (speedup 1.0000x reference)
#include <cuda_runtime.h>
#include <cstdint>

// Problem constants
#define BB   8
#define CC   256
#define DD_  16
#define HH_  32
#define WW_  32
#define SS   8
#define NN   16384            // D*H*W
#define PLANE 1024            // H*W

// Conv kernel tiling
#define CBLK 8                // channels per SMEM chunk
#define XROWS 34              // h = -1..32
#define XSTR  35              // padded w stride (conflict-free: 3h+w4 distinct mod 32)
#define XTILE (CBLK*3*XROWS*XSTR)          // 28560 floats
#define WTILE (CBLK*27*SS)                 // 1728 float2
#define CONV_SMEM ((XTILE + WTILE*2) * 4)  // 128064 bytes

// scratch: gated selection sel[b][s][n]
__device__ float g_sel[BB * SS * NN];

// ---- packed f32x2 helpers ----
__device__ __forceinline__ unsigned long long pack2(float a, float b) {
    unsigned long long r;
    asm("mov.b64 %0, {%1, %2};" : "=l"(r) : "f"(a), "f"(b));
    return r;
}
__device__ __forceinline__ void unpack2(unsigned long long v, float& a, float& b) {
    asm("mov.b64 {%0, %1}, %2;" : "=f"(a), "=f"(b) : "l"(v));
}
__device__ __forceinline__ void ffma2(unsigned long long& d, unsigned long long a,
                                      unsigned long long b) {
    asm("fma.rn.f32x2 %0, %1, %2, %0;" : "+l"(d) : "l"(a), "l"(b));
}

__device__ __forceinline__ float fast_sigmoid(float v) {
    return 1.0f / (1.0f + __expf(-v));
}

// ============================================================================
// K1: direct 3x3x3 conv (C=256 -> S=8) + bias + sigmoid -> g_sel
// grid = 128 (b*16 + d), block = 256 threads, each thread 4 w-positions.
// ============================================================================
__global__ void __launch_bounds__(256) conv_sigmoid_kernel(
    const float* __restrict__ x,     // [B,C,D,H,W]
    const float* __restrict__ Wc,    // [S,C,3,3,3]
    const float* __restrict__ bias)  // [S]
{
    extern __shared__ float smem[];
    float*  sx = smem;                               // [CBLK][3][34][35]
    float2* sw = (float2*)(smem + XTILE);            // [CBLK][27][8], dup'd weights

    const int b = blockIdx.x >> 4;
    const int d = blockIdx.x & 15;
    const int tid = threadIdx.x;
    const int h  = tid >> 3;            // 0..31
    const int w4 = (tid & 7) << 2;      // 0,4,...,28

    const float* xb = x + (size_t)b * CC * NN;

    unsigned long long acc[SS][2];
#pragma unroll
    for (int s = 0; s < SS; s++) { acc[s][0] = 0ull; acc[s][1] = 0ull; }

    for (int c0 = 0; c0 < CC; c0 += CBLK) {
        // ---- load weights (duplicated into float2 halves) ----
        for (int i = tid; i < CBLK * 27 * SS; i += 256) {
            int s = i & 7;
            int t = i >> 3;
            int off = t % 27;
            int c   = t / 27;
            float wv = Wc[((size_t)s * CC + (c0 + c)) * 27 + off];
            sw[(c * 27 + off) * SS + s] = make_float2(wv, wv);
        }
        // ---- load x tile with zero-padded halo ----
        for (int i = tid; i < XTILE; i += 256) {
            int wc = i % XSTR;
            int t  = i / XSTR;
            int hr = t % XROWS;
            t /= XROWS;
            int dd = t % 3;
            int c  = t / 3;
            int ds = d + dd - 1;
            int hs = hr - 1;
            int ws = wc - 1;
            float v = 0.0f;
            if ((unsigned)ds < (unsigned)DD_ && (unsigned)hs < (unsigned)HH_ &&
                (unsigned)ws < (unsigned)WW_) {
                v = xb[(size_t)(c0 + c) * NN + ds * PLANE + hs * WW_ + ws];
            }
            sx[i] = v;
        }
        __syncthreads();

        // ---- compute ----
#pragma unroll 1
        for (int c = 0; c < CBLK; c++) {
            const unsigned long long* wc2 =
                (const unsigned long long*)(sw + c * 27 * SS);
#pragma unroll
            for (int dd = 0; dd < 3; dd++) {
#pragma unroll
                for (int hh = 0; hh < 3; hh++) {
                    const float* r = &sx[((c * 3 + dd) * XROWS + (h + hh)) * XSTR + w4];
                    float x0 = r[0], x1 = r[1], x2 = r[2], x3 = r[3], x4 = r[4], x5 = r[5];
                    unsigned long long pr[5];
                    pr[0] = pack2(x0, x1);
                    pr[1] = pack2(x1, x2);
                    pr[2] = pack2(x2, x3);
                    pr[3] = pack2(x3, x4);
                    pr[4] = pack2(x4, x5);
#pragma unroll
                    for (int kw = 0; kw < 3; kw++) {
                        const unsigned long long* wp =
                            wc2 + ((dd * 3 + hh) * 3 + kw) * SS;
#pragma unroll
                        for (int s = 0; s < SS; s++) {
                            unsigned long long w2 = wp[s];   // LDS.64 broadcast
                            ffma2(acc[s][0], pr[kw],     w2);
                            ffma2(acc[s][1], pr[kw + 2], w2);
                        }
                    }
                }
            }
        }
        __syncthreads();
    }

    // ---- epilogue: bias + sigmoid, write sel ----
    const int nbase = d * PLANE + h * WW_ + w4;
#pragma unroll
    for (int s = 0; s < SS; s++) {
        float v0, v1, v2, v3;
        unpack2(acc[s][0], v0, v1);
        unpack2(acc[s][1], v2, v3);
        float bb = bias[s];
        float4 o;
        o.x = fast_sigmoid(v0 + bb);
        o.y = fast_sigmoid(v1 + bb);
        o.z = fast_sigmoid(v2 + bb);
        o.w = fast_sigmoid(v3 + bb);
        *(float4*)&g_sel[((size_t)(b * SS + s)) * NN + nbase] = o;
    }
}

// ============================================================================
// K2: out[b,s,c] = (1/N) * sum_n sel[b,s,n] * x[b,c,n]
// grid = 256 (b*32 + cblk), block = 256 (8 warps, one channel per warp).
// ============================================================================
#define K3CHUNK 1024

__global__ void __launch_bounds__(256) einsum_kernel(
    const float* __restrict__ x,     // [B,C,N]
    float* __restrict__ out)         // [B,S,C]
{
    __shared__ float ssel[SS][K3CHUNK];   // 32 KB

    const int b    = blockIdx.x >> 5;
    const int cblk = blockIdx.x & 31;
    const int tid  = threadIdx.x;
    const int warp = tid >> 5;
    const int lane = tid & 31;
    const int c    = cblk * 8 + warp;

    const float* xc   = x + ((size_t)(b * CC + c)) * NN;
    const float* selb = g_sel + (size_t)b * SS * NN;

    unsigned long long acc[SS];
#pragma unroll
    for (int s = 0; s < SS; s++) acc[s] = 0ull;

    for (int n0 = 0; n0 < NN; n0 += K3CHUNK) {
        __syncthreads();   // prior reads done before overwrite
        for (int j = tid; j < SS * K3CHUNK; j += 256) {
            int s  = j >> 10;
            int nn = j & (K3CHUNK - 1);
            ssel[s][nn] = selb[(size_t)s * NN + n0 + nn];
        }
        __syncthreads();

#pragma unroll
        for (int i = 0; i < K3CHUNK / 128; i++) {
            int nl = i * 128 + lane * 4;
            float4 xv = *(const float4*)(xc + n0 + nl);
            unsigned long long x01 = pack2(xv.x, xv.y);
            unsigned long long x23 = pack2(xv.z, xv.w);
#pragma unroll
            for (int s = 0; s < SS; s++) {
                float4 sv = *(const float4*)(&ssel[s][nl]);  // LDS.128 conflict-free
                ffma2(acc[s], pack2(sv.x, sv.y), x01);
                ffma2(acc[s], pack2(sv.z, sv.w), x23);
            }
        }
    }

    // reduce within warp, write
#pragma unroll
    for (int s = 0; s < SS; s++) {
        float a, bb;
        unpack2(acc[s], a, bb);
        float v = a + bb;
#pragma unroll
        for (int m = 16; m > 0; m >>= 1)
            v += __shfl_xor_sync(0xffffffffu, v, m);
        if (lane == 0)
            out[(size_t)b * SS * CC + s * CC + c] = v * (1.0f / (float)NN);
    }
}

// ============================================================================
extern "C" void kernel_launch(void* const* d_in, const int* in_sizes, int n_in,
                              void* d_out, int out_size) {
    const float* x    = (const float*)d_in[0];   // [8,256,16,32,32]
    const float* Wc   = (const float*)d_in[1];   // [8,256,3,3,3]
    const float* bias = (const float*)d_in[2];   // [8]
    float* out = (float*)d_out;                  // [8,8,256]

    cudaFuncSetAttribute(conv_sigmoid_kernel,
                         cudaFuncAttributeMaxDynamicSharedMemorySize, CONV_SMEM);

    conv_sigmoid_kernel<<<BB * DD_, 256, CONV_SMEM>>>(x, Wc, bias);
    einsum_kernel<<<BB * 32, 256>>>(x, out);
}

// round 2
// speedup vs baseline: 2.5409x; 2.5409x over previous
#include <cuda_runtime.h>
#include <cstdint>

// Problem constants
#define BB   8
#define CC   256
#define DD_  16
#define HH_  32
#define WW_  32
#define SS   8
#define NN   16384            // D*H*W
#define PLANE 1024            // H*W

// Conv tiling
#define CBLK 8                 // channels per SMEM chunk
#define XROWS 34               // rows: h = -1..32
#define XSTR  35               // padded w stride (banks: 3h+4k distinct mod 32)
#define XPLANE (XROWS*XSTR)    // 1190
#define XTILE (CBLK*3*XPLANE)  // 28560 floats
#define WTILE (CBLK*27*SS)     // 1728 floats (non-duplicated)
#define CONV_SMEM ((XTILE + WTILE) * 4)   // 121152 bytes

#define NSPLIT 4
#define K3CHUNK 512

// scratch
__device__ float g_sel[BB * SS * NN];
__device__ float g_partial[NSPLIT * BB * SS * CC];

typedef unsigned long long ull;

// ---- packed f32x2 helpers ----
__device__ __forceinline__ ull pack2(float a, float b) {
    ull r;
    asm("mov.b64 %0, {%1, %2};" : "=l"(r) : "f"(a), "f"(b));
    return r;
}
__device__ __forceinline__ void unpack2(ull v, float& a, float& b) {
    asm("mov.b64 {%0, %1}, %2;" : "=f"(a), "=f"(b) : "l"(v));
}
__device__ __forceinline__ void ffma2(ull& d, ull a, ull b) {
    asm("fma.rn.f32x2 %0, %1, %2, %0;" : "+l"(d) : "l"(a), "l"(b));
}
__device__ __forceinline__ float fast_sigmoid(float v) {
    return 1.0f / (1.0f + __expf(-v));
}

// ============================================================================
// K1: direct 3x3x3 conv (C=256 -> S=8) + bias + sigmoid -> g_sel
// grid = 128 (b*16 + d), block = 256.  Thread: (h, 4 w-positions).
// s-channel lives on the f32x2 lane: acc[sp][j] = (out_{2sp}, out_{2sp+1})
// at position j.  Weights fetched 8-at-a-time via LDS.128 broadcast.
// ============================================================================
__global__ void __launch_bounds__(256) conv_sigmoid_kernel(
    const float* __restrict__ x,     // [B,C,D,H,W]
    const float* __restrict__ Wc,    // [S,C,3,3,3]
    const float* __restrict__ bias)  // [S]
{
    extern __shared__ float smem[];
    float* sx  = smem;               // [CBLK*3][34][35], borders stay zero
    float* swf = smem + XTILE;       // [CBLK][27][8]  (c, tap, s)

    const int b   = blockIdx.x >> 4;
    const int d   = blockIdx.x & 15;
    const int tid = threadIdx.x;
    const int h   = tid >> 3;        // 0..31
    const int g   = tid & 7;         // col group, w4 = 4g
    const int w4  = g << 2;

    const float* xb = x + (size_t)b * CC * NN;

    // zero the whole frame once; interior rewritten per chunk, borders stay 0
    for (int i = tid; i < XTILE; i += 256) sx[i] = 0.0f;

    ull acc[4][4];
#pragma unroll
    for (int sp = 0; sp < 4; sp++)
#pragma unroll
        for (int j = 0; j < 4; j++) acc[sp][j] = 0ull;

    for (int c0 = 0; c0 < CC; c0 += CBLK) {
        __syncthreads();   // prior compute reads (or zero-fill) complete

        // ---- weights: coalesced, layout [c][tap][s] ----
        for (int i = tid; i < WTILE; i += 256) {
            int s = i / 216;                 // 216 = 8*27
            int r = i - s * 216;             // r = c*27 + tap
            swf[r * 8 + s] = Wc[(size_t)s * (CC * 27) + c0 * 27 + r];
        }

        // ---- x interior: 24 planes, one float4 per thread per plane ----
#pragma unroll
        for (int p = 0; p < CBLK * 3; p++) {
            const int c  = p / 3;
            const int dd = p - c * 3;
            const int ds = d + dd - 1;
            float4 v = make_float4(0.f, 0.f, 0.f, 0.f);
            if ((unsigned)ds < (unsigned)DD_)
                v = *(const float4*)(xb + (size_t)(c0 + c) * NN +
                                     ds * PLANE + h * WW_ + w4);
            float* dst = &sx[p * XPLANE + (h + 1) * XSTR + 1 + w4];
            dst[0] = v.x; dst[1] = v.y; dst[2] = v.z; dst[3] = v.w;
        }
        __syncthreads();

        // ---- compute ----
#pragma unroll 1
        for (int c = 0; c < CBLK; c++) {
            const float* wcb = &swf[c * 27 * 8];
#pragma unroll
            for (int dd = 0; dd < 3; dd++) {
#pragma unroll
                for (int hh = 0; hh < 3; hh++) {
                    const float* r =
                        &sx[((c * 3 + dd) * XROWS + h + hh) * XSTR + w4];
                    // duplicated x values (6 cols cover 4 positions x 3 taps)
                    ull dx[6];
#pragma unroll
                    for (int k = 0; k < 6; k++) dx[k] = pack2(r[k], r[k]);

                    const ulonglong2* wp = (const ulonglong2*)
                        (wcb + ((dd * 3 + hh) * 3) * 8);
#pragma unroll
                    for (int kw = 0; kw < 3; kw++) {
                        ulonglong2 wa = wp[2 * kw];       // s0..s3
                        ulonglong2 wb = wp[2 * kw + 1];   // s4..s7
#pragma unroll
                        for (int j = 0; j < 4; j++) {
                            ull a = dx[j + kw];
                            ffma2(acc[0][j], a, wa.x);
                            ffma2(acc[1][j], a, wa.y);
                            ffma2(acc[2][j], a, wb.x);
                            ffma2(acc[3][j], a, wb.y);
                        }
                    }
                }
            }
        }
    }

    // ---- epilogue: bias + sigmoid, write sel ----
    const int nbase = d * PLANE + h * WW_ + w4;
#pragma unroll
    for (int sp = 0; sp < 4; sp++) {
        float lo[4], hi[4];
#pragma unroll
        for (int j = 0; j < 4; j++) unpack2(acc[sp][j], lo[j], hi[j]);

        float b0 = bias[2 * sp];
        float b1 = bias[2 * sp + 1];
        float4 o0, o1;
        o0.x = fast_sigmoid(lo[0] + b0); o0.y = fast_sigmoid(lo[1] + b0);
        o0.z = fast_sigmoid(lo[2] + b0); o0.w = fast_sigmoid(lo[3] + b0);
        o1.x = fast_sigmoid(hi[0] + b1); o1.y = fast_sigmoid(hi[1] + b1);
        o1.z = fast_sigmoid(hi[2] + b1); o1.w = fast_sigmoid(hi[3] + b1);
        *(float4*)&g_sel[((size_t)(b * SS + 2 * sp)) * NN + nbase]     = o0;
        *(float4*)&g_sel[((size_t)(b * SS + 2 * sp + 1)) * NN + nbase] = o1;
    }
}

// ============================================================================
// K2: partial[v,b,s,c] = sum_{n in split v} sel[b,s,n] * x[b,c,n]
// grid = B*32*NSPLIT = 1024, block 256 (8 warps, one channel per warp).
// ============================================================================
__global__ void __launch_bounds__(256) einsum_kernel(
    const float* __restrict__ x)     // [B,C,N]
{
    __shared__ float ssel[SS][K3CHUNK];   // 16 KB

    const int idx  = blockIdx.x;
    const int v    = idx & (NSPLIT - 1);
    const int cblk = (idx >> 2) & 31;
    const int b    = idx >> 7;
    const int tid  = threadIdx.x;
    const int warp = tid >> 5;
    const int lane = tid & 31;
    const int c    = cblk * 8 + warp;

    const int nlo = v * (NN / NSPLIT);
    const float* xc   = x + ((size_t)(b * CC + c)) * NN;
    const float* selb = g_sel + (size_t)b * SS * NN;

    ull acc[SS];
#pragma unroll
    for (int s = 0; s < SS; s++) acc[s] = 0ull;

    for (int n0 = nlo; n0 < nlo + NN / NSPLIT; n0 += K3CHUNK) {
        __syncthreads();
        for (int j = tid; j < SS * K3CHUNK; j += 256) {
            int s  = j >> 9;                    // K3CHUNK = 512
            int nn = j & (K3CHUNK - 1);
            ssel[s][nn] = selb[(size_t)s * NN + n0 + nn];
        }
        __syncthreads();

#pragma unroll
        for (int i = 0; i < K3CHUNK / 128; i++) {
            int nl = i * 128 + lane * 4;
            float4 xv = *(const float4*)(xc + n0 + nl);
            ull x01 = pack2(xv.x, xv.y);
            ull x23 = pack2(xv.z, xv.w);
#pragma unroll
            for (int s = 0; s < SS; s++) {
                float4 sv = *(const float4*)(&ssel[s][nl]);
                ffma2(acc[s], pack2(sv.x, sv.y), x01);
                ffma2(acc[s], pack2(sv.z, sv.w), x23);
            }
        }
    }

#pragma unroll
    for (int s = 0; s < SS; s++) {
        float a, bb;
        unpack2(acc[s], a, bb);
        float val = a + bb;
#pragma unroll
        for (int m = 16; m > 0; m >>= 1)
            val += __shfl_xor_sync(0xffffffffu, val, m);
        if (lane == 0)
            g_partial[(((size_t)v * BB + b) * SS + s) * CC + c] = val;
    }
}

// ============================================================================
// K3: out[i] = sum_v partial[v][i] / N     (i over B*S*C = 16384)
// ============================================================================
__global__ void __launch_bounds__(256) reduce_kernel(float* __restrict__ out) {
    int i = blockIdx.x * 256 + threadIdx.x;
    if (i < BB * SS * CC) {
        float s = 0.f;
#pragma unroll
        for (int v = 0; v < NSPLIT; v++)
            s += g_partial[(size_t)v * (BB * SS * CC) + i];
        out[i] = s * (1.0f / (float)NN);
    }
}

// ============================================================================
extern "C" void kernel_launch(void* const* d_in, const int* in_sizes, int n_in,
                              void* d_out, int out_size) {
    const float* x    = (const float*)d_in[0];   // [8,256,16,32,32]
    const float* Wc   = (const float*)d_in[1];   // [8,256,3,3,3]
    const float* bias = (const float*)d_in[2];   // [8]
    float* out = (float*)d_out;                  // [8,8,256]

    cudaFuncSetAttribute(conv_sigmoid_kernel,
                         cudaFuncAttributeMaxDynamicSharedMemorySize, CONV_SMEM);

    conv_sigmoid_kernel<<<BB * DD_, 256, CONV_SMEM>>>(x, Wc, bias);
    einsum_kernel<<<BB * 32 * NSPLIT, 256>>>(x);
    reduce_kernel<<<(BB * SS * CC + 255) / 256, 256>>>(out);
}

// round 3
// speedup vs baseline: 2.5607x; 1.0078x over previous
#include <cuda_runtime.h>
#include <cstdint>

// Problem constants
#define BB   8
#define CC   256
#define DD_  16
#define HH_  32
#define WW_  32
#define SS   8
#define NN   16384            // D*H*W
#define PLANE 1024            // H*W

// Conv tiling
#define CBLK 8                 // channels per SMEM chunk
#define XROWS 34               // rows: h = -1..32
#define XSTR  35               // padded w stride (banks: 3h+4k distinct mod 32)
#define XPLANE (XROWS*XSTR)    // 1190
#define XTILE (CBLK*3*XPLANE)  // 28560 floats
#define WTILE (CBLK*27*SS)     // 1728 floats (non-duplicated)
#define CONV_SMEM ((XTILE + WTILE) * 4)   // 121152 bytes

#define NSPLIT 4
#define K3CHUNK 512

// scratch
__device__ float g_sel[BB * SS * NN];
__device__ float g_partial[NSPLIT * BB * SS * CC];

typedef unsigned long long ull;

// ---- packed f32x2 helpers ----
__device__ __forceinline__ ull pack2(float a, float b) {
    ull r;
    asm("mov.b64 %0, {%1, %2};" : "=l"(r) : "f"(a), "f"(b));
    return r;
}
__device__ __forceinline__ void unpack2(ull v, float& a, float& b) {
    asm("mov.b64 {%0, %1}, %2;" : "=f"(a), "=f"(b) : "l"(v));
}
__device__ __forceinline__ void ffma2(ull& d, ull a, ull b) {
    asm("fma.rn.f32x2 %0, %1, %2, %0;" : "+l"(d) : "l"(a), "l"(b));
}
__device__ __forceinline__ float fast_sigmoid(float v) {
    return 1.0f / (1.0f + __expf(-v));
}

// ============================================================================
// K1: direct 3x3x3 conv (C=256 -> S=8) + bias + sigmoid -> g_sel
// grid = 128 (b*16 + d), block = 256.  Thread: (h, 4 w-positions).
// s-channel lives on the f32x2 lane: acc[sp][j] = (out_{2sp}, out_{2sp+1})
// at position j.  Weights fetched 8-at-a-time via LDS.128 broadcast.
// ============================================================================
__global__ void __launch_bounds__(256) conv_sigmoid_kernel(
    const float* __restrict__ x,     // [B,C,D,H,W]
    const float* __restrict__ Wc,    // [S,C,3,3,3]
    const float* __restrict__ bias)  // [S]
{
    extern __shared__ float smem[];
    float* sx  = smem;               // [CBLK*3][34][35], borders stay zero
    float* swf = smem + XTILE;       // [CBLK][27][8]  (c, tap, s)

    const int b   = blockIdx.x >> 4;
    const int d   = blockIdx.x & 15;
    const int tid = threadIdx.x;
    const int h   = tid >> 3;        // 0..31
    const int g   = tid & 7;         // col group, w4 = 4g
    const int w4  = g << 2;

    const float* xb = x + (size_t)b * CC * NN;

    // zero the whole frame once; interior rewritten per chunk, borders stay 0
    for (int i = tid; i < XTILE; i += 256) sx[i] = 0.0f;

    ull acc[4][4];
#pragma unroll
    for (int sp = 0; sp < 4; sp++)
#pragma unroll
        for (int j = 0; j < 4; j++) acc[sp][j] = 0ull;

    for (int c0 = 0; c0 < CC; c0 += CBLK) {
        __syncthreads();   // prior compute reads (or zero-fill) complete

        // ---- weights: coalesced, layout [c][tap][s] ----
        for (int i = tid; i < WTILE; i += 256) {
            int s = i / 216;                 // 216 = 8*27
            int r = i - s * 216;             // r = c*27 + tap
            swf[r * 8 + s] = Wc[(size_t)s * (CC * 27) + c0 * 27 + r];
        }

        // ---- x interior: 24 planes, one float4 per thread per plane ----
#pragma unroll
        for (int p = 0; p < CBLK * 3; p++) {
            const int c  = p / 3;
            const int dd = p - c * 3;
            const int ds = d + dd - 1;
            float4 v = make_float4(0.f, 0.f, 0.f, 0.f);
            if ((unsigned)ds < (unsigned)DD_)
                v = *(const float4*)(xb + (size_t)(c0 + c) * NN +
                                     ds * PLANE + h * WW_ + w4);
            float* dst = &sx[p * XPLANE + (h + 1) * XSTR + 1 + w4];
            dst[0] = v.x; dst[1] = v.y; dst[2] = v.z; dst[3] = v.w;
        }
        __syncthreads();

        // ---- compute ----
#pragma unroll 1
        for (int c = 0; c < CBLK; c++) {
            const float* wcb = &swf[c * 27 * 8];
#pragma unroll
            for (int dd = 0; dd < 3; dd++) {
#pragma unroll
                for (int hh = 0; hh < 3; hh++) {
                    const float* r =
                        &sx[((c * 3 + dd) * XROWS + h + hh) * XSTR + w4];
                    // duplicated x values (6 cols cover 4 positions x 3 taps)
                    ull dx[6];
#pragma unroll
                    for (int k = 0; k < 6; k++) dx[k] = pack2(r[k], r[k]);

                    const ulonglong2* wp = (const ulonglong2*)
                        (wcb + ((dd * 3 + hh) * 3) * 8);
#pragma unroll
                    for (int kw = 0; kw < 3; kw++) {
                        ulonglong2 wa = wp[2 * kw];       // s0..s3
                        ulonglong2 wb = wp[2 * kw + 1];   // s4..s7
#pragma unroll
                        for (int j = 0; j < 4; j++) {
                            ull a = dx[j + kw];
                            ffma2(acc[0][j], a, wa.x);
                            ffma2(acc[1][j], a, wa.y);
                            ffma2(acc[2][j], a, wb.x);
                            ffma2(acc[3][j], a, wb.y);
                        }
                    }
                }
            }
        }
    }

    // ---- epilogue: bias + sigmoid, write sel ----
    const int nbase = d * PLANE + h * WW_ + w4;
#pragma unroll
    for (int sp = 0; sp < 4; sp++) {
        float lo[4], hi[4];
#pragma unroll
        for (int j = 0; j < 4; j++) unpack2(acc[sp][j], lo[j], hi[j]);

        float b0 = bias[2 * sp];
        float b1 = bias[2 * sp + 1];
        float4 o0, o1;
        o0.x = fast_sigmoid(lo[0] + b0); o0.y = fast_sigmoid(lo[1] + b0);
        o0.z = fast_sigmoid(lo[2] + b0); o0.w = fast_sigmoid(lo[3] + b0);
        o1.x = fast_sigmoid(hi[0] + b1); o1.y = fast_sigmoid(hi[1] + b1);
        o1.z = fast_sigmoid(hi[2] + b1); o1.w = fast_sigmoid(hi[3] + b1);
        *(float4*)&g_sel[((size_t)(b * SS + 2 * sp)) * NN + nbase]     = o0;
        *(float4*)&g_sel[((size_t)(b * SS + 2 * sp + 1)) * NN + nbase] = o1;
    }
}

// ============================================================================
// K2: partial[v,b,s,c] = sum_{n in split v} sel[b,s,n] * x[b,c,n]
// grid = B*32*NSPLIT = 1024, block 256 (8 warps, one channel per warp).
// ============================================================================
__global__ void __launch_bounds__(256) einsum_kernel(
    const float* __restrict__ x)     // [B,C,N]
{
    __shared__ float ssel[SS][K3CHUNK];   // 16 KB

    const int idx  = blockIdx.x;
    const int v    = idx & (NSPLIT - 1);
    const int cblk = (idx >> 2) & 31;
    const int b    = idx >> 7;
    const int tid  = threadIdx.x;
    const int warp = tid >> 5;
    const int lane = tid & 31;
    const int c    = cblk * 8 + warp;

    const int nlo = v * (NN / NSPLIT);
    const float* xc   = x + ((size_t)(b * CC + c)) * NN;
    const float* selb = g_sel + (size_t)b * SS * NN;

    ull acc[SS];
#pragma unroll
    for (int s = 0; s < SS; s++) acc[s] = 0ull;

    for (int n0 = nlo; n0 < nlo + NN / NSPLIT; n0 += K3CHUNK) {
        __syncthreads();
        for (int j = tid; j < SS * K3CHUNK; j += 256) {
            int s  = j >> 9;                    // K3CHUNK = 512
            int nn = j & (K3CHUNK - 1);
            ssel[s][nn] = selb[(size_t)s * NN + n0 + nn];
        }
        __syncthreads();

#pragma unroll
        for (int i = 0; i < K3CHUNK / 128; i++) {
            int nl = i * 128 + lane * 4;
            float4 xv = *(const float4*)(xc + n0 + nl);
            ull x01 = pack2(xv.x, xv.y);
            ull x23 = pack2(xv.z, xv.w);
#pragma unroll
            for (int s = 0; s < SS; s++) {
                float4 sv = *(const float4*)(&ssel[s][nl]);
                ffma2(acc[s], pack2(sv.x, sv.y), x01);
                ffma2(acc[s], pack2(sv.z, sv.w), x23);
            }
        }
    }

#pragma unroll
    for (int s = 0; s < SS; s++) {
        float a, bb;
        unpack2(acc[s], a, bb);
        float val = a + bb;
#pragma unroll
        for (int m = 16; m > 0; m >>= 1)
            val += __shfl_xor_sync(0xffffffffu, val, m);
        if (lane == 0)
            g_partial[(((size_t)v * BB + b) * SS + s) * CC + c] = val;
    }
}

// ============================================================================
// K3: out[i] = sum_v partial[v][i] / N     (i over B*S*C = 16384)
// ============================================================================
__global__ void __launch_bounds__(256) reduce_kernel(float* __restrict__ out) {
    int i = blockIdx.x * 256 + threadIdx.x;
    if (i < BB * SS * CC) {
        float s = 0.f;
#pragma unroll
        for (int v = 0; v < NSPLIT; v++)
            s += g_partial[(size_t)v * (BB * SS * CC) + i];
        out[i] = s * (1.0f / (float)NN);
    }
}

// ============================================================================
extern "C" void kernel_launch(void* const* d_in, const int* in_sizes, int n_in,
                              void* d_out, int out_size) {
    const float* x    = (const float*)d_in[0];   // [8,256,16,32,32]
    const float* Wc   = (const float*)d_in[1];   // [8,256,3,3,3]
    const float* bias = (const float*)d_in[2];   // [8]
    float* out = (float*)d_out;                  // [8,8,256]

    cudaFuncSetAttribute(conv_sigmoid_kernel,
                         cudaFuncAttributeMaxDynamicSharedMemorySize, CONV_SMEM);

    conv_sigmoid_kernel<<<BB * DD_, 256, CONV_SMEM>>>(x, Wc, bias);
    einsum_kernel<<<BB * 32 * NSPLIT, 256>>>(x);
    reduce_kernel<<<(BB * SS * CC + 255) / 256, 256>>>(out);
}

// round 5
// speedup vs baseline: 5.2307x; 2.0427x over previous
#include <cuda_runtime.h>
#include <cuda_bf16.h>
#include <cuda_fp16.h>
#include <cstdint>
#include <cstring>

#define BB   8
#define CC   256
#define DD_  16
#define HH_  32
#define WW_  32
#define SS   8
#define NN   16384
#define PLANE 1024
#define NTAP 27
#define BROWS 224          // padded mo rows (28 tiles of 8)

// GEMM dynamic smem layout (bytes)
#define XH_OFF 0           // 128 rows x 128B (bf16 hi of x tile)
#define XL_OFF 16384       // 128 rows x 128B (bf16 lo)
#define BH_OFF 32768       // 224 rows x 128B (W' hi, one kchunk)
#define BL_OFF 61440       // 224 rows x 128B (W' lo)
#define GEMM_SMEM 90112

#define NSPLIT 4
#define K3CHUNK 512

typedef unsigned int u32;
typedef unsigned long long ull;

// ---------------- scratch ----------------
__device__ __half g_u3[(size_t)BB * NTAP * NN * SS];     // [b][tap][m][s] fp16
__device__ float  g_sel[BB * SS * NN];
__device__ float  g_partial[NSPLIT * BB * SS * CC];
__device__ int4   g_Bh4[4 * BROWS * 8];                  // 4 kchunks x 224 rows x 128B (swizzled)
__device__ int4   g_Bl4[4 * BROWS * 8];

// ---------------- helpers ----------------
__device__ __forceinline__ u32 smem_u32(const void* p) {
    u32 a;
    asm("{ .reg .u64 t; cvta.to.shared.u64 t, %1; cvt.u32.u64 %0, t; }"
        : "=r"(a) : "l"(p));
    return a;
}
__device__ __forceinline__ void ldm4(u32* r, u32 addr) {
    asm volatile("ldmatrix.sync.aligned.m8n8.x4.shared.b16 {%0,%1,%2,%3}, [%4];"
                 : "=r"(r[0]), "=r"(r[1]), "=r"(r[2]), "=r"(r[3]) : "r"(addr));
}
__device__ __forceinline__ void mma16816(float* c, const u32* a, const u32* b) {
    asm volatile("mma.sync.aligned.m16n8k16.row.col.f32.bf16.bf16.f32 "
                 "{%0,%1,%2,%3}, {%4,%5,%6,%7}, {%8,%9}, {%0,%1,%2,%3};"
                 : "+f"(c[0]), "+f"(c[1]), "+f"(c[2]), "+f"(c[3])
                 : "r"(a[0]), "r"(a[1]), "r"(a[2]), "r"(a[3]),
                   "r"(b[0]), "r"(b[1]));
}
__device__ __forceinline__ ull pack2(float a, float b) {
    ull r; asm("mov.b64 %0, {%1, %2};" : "=l"(r) : "f"(a), "f"(b)); return r;
}
__device__ __forceinline__ void unpack2(ull v, float& a, float& b) {
    asm("mov.b64 {%0, %1}, %2;" : "=f"(a), "=f"(b) : "l"(v));
}
__device__ __forceinline__ void ffma2(ull& d, ull a, ull b) {
    asm("fma.rn.f32x2 %0, %1, %2, %0;" : "+l"(d) : "l"(a), "l"(b));
}
__device__ __forceinline__ float fast_sigmoid(float v) {
    return 1.0f / (1.0f + __expf(-v));
}

// ============================================================================
// K0: prep W' -> bf16 hi/lo SW128-swizzled smem images per kchunk.
// grid = 224 (mo rows incl. pad), block = 256 (c).
// Image row mo holds W'[mo][k] for the kchunk, 64 bf16 = 128B (one swizzle atom).
// ============================================================================
__global__ void __launch_bounds__(256) prep_kernel(const float* __restrict__ Wc) {
    const int mo = blockIdx.x;
    const int c  = threadIdx.x;
    float w = 0.0f;
    if (mo < 216) {
        int s = mo & 7, tap = mo >> 3;
        w = Wc[((size_t)s * CC + c) * 27 + tap];
    }
    __nv_bfloat16 h = __float2bfloat16(w);
    float r = w - __bfloat162float(h);
    __nv_bfloat16 l = __float2bfloat16(r);

    const int kc = c >> 6;
    const u32 kb = (u32)((c & 63) * 2) ^ (u32)((mo & 7) << 4);  // SW128 within row
    const size_t idx = (size_t)kc * (BROWS * 64) + ((u32)mo * 128 + kb) / 2;
    unsigned short hb, lb;
    memcpy(&hb, &h, 2); memcpy(&lb, &l, 2);
    ((unsigned short*)g_Bh4)[idx] = hb;
    ((unsigned short*)g_Bl4)[idx] = lb;
}

// ============================================================================
// K1: GEMM u[m][mo] = sum_k x[k][m] * W'[mo][k]  via mma.sync bf16 triple-split
// grid = B*128 = 1024 CTAs, block = 256 (8 warps = 4 m-groups x 2 n-halves).
// Warp: 2 m16 tiles x 14 n8 tiles. Epilogue: fp16 -> g_u3[b][tap][m][s].
// ============================================================================
__global__ void __launch_bounds__(256) gemm_kernel(const float* __restrict__ x) {
    extern __shared__ char smem[];
    const u32 sb = smem_u32(smem);
    const int tid = threadIdx.x, lane = tid & 31, warp = tid >> 5;
    const int mg = warp & 3, nh = warp >> 2;
    const int b  = blockIdx.x >> 7;
    const int n0 = (blockIdx.x & 127) * 128;

    float acc[7][2][2][4];
#pragma unroll
    for (int p = 0; p < 7; p++)
#pragma unroll
        for (int t = 0; t < 2; t++)
#pragma unroll
            for (int m = 0; m < 2; m++)
#pragma unroll
                for (int i = 0; i < 4; i++) acc[p][t][m][i] = 0.0f;

    // lane-constant ldmatrix address parts (SW128 xor mask = (lane&7)<<4)
    const u32 xm     = (u32)(lane & 7) << 4;
    const int arow   = (lane & 7) + ((lane >> 3) & 1) * 8;
    const u32 a_ksel = (u32)((lane >> 4) & 1) * 16;
    const u32 b_ksel = (u32)((lane >> 3) & 1) * 16;
    const int btile  = (lane >> 4);        // which tile of the pair
    const int brow   = lane & 7;

    const int mt0 = mg * 32;
    const u32 aXh0 = sb + XH_OFF + (u32)(mt0 + arow) * 128;
    const u32 aXh1 = aXh0 + 16 * 128;
    const u32 aXl0 = sb + XL_OFF + (u32)(mt0 + arow) * 128;
    const u32 aXl1 = aXl0 + 16 * 128;

    const float* xb = x + (size_t)b * CC * NN + n0;
    const int cm  = tid & 127;             // conversion: m row
    const int ckh = tid >> 7;              // conversion: k half of chunk
    const u32 cxm = (u32)(cm & 7) << 4;

#pragma unroll 1
    for (int kc = 0; kc < 4; kc++) {
        __syncthreads();
        // ---- copy W' kchunk images (pre-swizzled) ----
        {
            const int4* srcH = g_Bh4 + kc * (BROWS * 8);
            const int4* srcL = g_Bl4 + kc * (BROWS * 8);
            int4* dH = (int4*)(smem + BH_OFF);
            int4* dL = (int4*)(smem + BL_OFF);
#pragma unroll
            for (int i = 0; i < 7; i++) {
                dH[tid + i * 256] = srcH[tid + i * 256];
                dL[tid + i * 256] = srcL[tid + i * 256];
            }
        }
        // ---- load x (coalesced), split bf16 hi/lo, swizzled smem stores ----
        {
            const float* xp = xb + (size_t)(kc * 64 + ckh * 32) * NN + cm;
#pragma unroll
            for (int u = 0; u < 16; u++) {
                float v0 = xp[(size_t)(2 * u) * NN];
                float v1 = xp[(size_t)(2 * u + 1) * NN];
                __nv_bfloat162 h2 = __floats2bfloat162_rn(v0, v1);
                float r0 = v0 - __bfloat162float(h2.x);
                float r1 = v1 - __bfloat162float(h2.y);
                __nv_bfloat162 l2 = __floats2bfloat162_rn(r0, r1);
                u32 hp, lp;
                memcpy(&hp, &h2, 4); memcpy(&lp, &l2, 4);
                u32 kb = (u32)(ckh * 64 + u * 4) ^ cxm;
                *(u32*)(smem + XH_OFF + cm * 128 + kb) = hp;
                *(u32*)(smem + XL_OFF + cm * 128 + kb) = lp;
            }
        }
        __syncthreads();

        // ---- 4 k16 steps ----
#pragma unroll
        for (int j = 0; j < 4; j++) {
            const u32 ka  = ((u32)(j * 32) + a_ksel) ^ xm;
            const u32 kb2 = ((u32)(j * 32) + b_ksel) ^ xm;
            u32 Ah0[4], Ah1[4], Al0[4], Al1[4];
            ldm4(Ah0, aXh0 + ka); ldm4(Ah1, aXh1 + ka);
            ldm4(Al0, aXl0 + ka); ldm4(Al1, aXl1 + ka);
#pragma unroll
            for (int p = 0; p < 7; p++) {   // Wh: used by xh and xl passes
                const int tile = nh * 14 + 2 * p + btile;
                u32 Bf[4];
                ldm4(Bf, sb + BH_OFF + (u32)(tile * 8 + brow) * 128 + kb2);
                mma16816(acc[p][0][0], Ah0, Bf);
                mma16816(acc[p][0][1], Ah1, Bf);
                mma16816(acc[p][1][0], Ah0, Bf + 2);
                mma16816(acc[p][1][1], Ah1, Bf + 2);
                mma16816(acc[p][0][0], Al0, Bf);
                mma16816(acc[p][0][1], Al1, Bf);
                mma16816(acc[p][1][0], Al0, Bf + 2);
                mma16816(acc[p][1][1], Al1, Bf + 2);
            }
#pragma unroll
            for (int p = 0; p < 7; p++) {   // Wl: xh pass only
                const int tile = nh * 14 + 2 * p + btile;
                u32 Bf[4];
                ldm4(Bf, sb + BL_OFF + (u32)(tile * 8 + brow) * 128 + kb2);
                mma16816(acc[p][0][0], Ah0, Bf);
                mma16816(acc[p][0][1], Ah1, Bf);
                mma16816(acc[p][1][0], Ah0, Bf + 2);
                mma16816(acc[p][1][1], Ah1, Bf + 2);
            }
        }
    }

    // ---- epilogue: fp16 stores, fully coalesced (tile == tap) ----
    const int mrow = lane >> 2;
    const int q    = lane & 3;
    u32* up = (u32*)g_u3;
#pragma unroll
    for (int p = 0; p < 7; p++)
#pragma unroll
        for (int tt = 0; tt < 2; tt++) {
            const int tile = nh * 14 + 2 * p + tt;
            if (tile >= NTAP) continue;     // pad tile
#pragma unroll
            for (int mi = 0; mi < 2; mi++) {
                const float* cf = acc[p][tt][mi];
                const int m = n0 + mt0 + mi * 16 + mrow;
                const size_t base = ((size_t)(b * NTAP + tile) * NN + m) * 4 + q;
                __half2 h01 = __floats2half2_rn(cf[0], cf[1]);
                __half2 h23 = __floats2half2_rn(cf[2], cf[3]);
                u32 w01, w23;
                memcpy(&w01, &h01, 4); memcpy(&w23, &h23, 4);
                up[base]      = w01;
                up[base + 32] = w23;        // m+8 row
            }
        }
}

// ============================================================================
// K2: shift-add taps + bias + sigmoid -> g_sel
// thread = one (b, n); 27 coalesced 16B tap-slice loads.
// ============================================================================
__global__ void __launch_bounds__(256) shiftadd_kernel(const float* __restrict__ bias) {
    const int gi = blockIdx.x * 256 + threadIdx.x;
    const int b = gi >> 14, n = gi & (NN - 1);
    const int d = n >> 10, h = (n >> 5) & 31, w = n & 31;

    float acc[SS];
#pragma unroll
    for (int s = 0; s < SS; s++) acc[s] = bias[s];

    const uint4* ub = (const uint4*)g_u3 + (size_t)b * NTAP * NN;

#pragma unroll
    for (int kd = 0; kd < 3; kd++) {
        const int dd = d + kd - 1;
        if ((unsigned)dd >= (unsigned)DD_) continue;
#pragma unroll
        for (int kh = 0; kh < 3; kh++) {
            const int hh = h + kh - 1;
            if ((unsigned)hh >= (unsigned)HH_) continue;
#pragma unroll
            for (int kw = 0; kw < 3; kw++) {
                const int ww = w + kw - 1;
                if ((unsigned)ww >= (unsigned)WW_) continue;
                const int tap = (kd * 3 + kh) * 3 + kw;
                const int m = dd * PLANE + hh * WW_ + ww;
                uint4 v = ub[(size_t)tap * NN + m];
                __half2 p0, p1, p2, p3;
                memcpy(&p0, &v.x, 4); memcpy(&p1, &v.y, 4);
                memcpy(&p2, &v.z, 4); memcpy(&p3, &v.w, 4);
                float2 f0 = __half22float2(p0), f1 = __half22float2(p1);
                float2 f2 = __half22float2(p2), f3 = __half22float2(p3);
                acc[0] += f0.x; acc[1] += f0.y; acc[2] += f1.x; acc[3] += f1.y;
                acc[4] += f2.x; acc[5] += f2.y; acc[6] += f3.x; acc[7] += f3.y;
            }
        }
    }
#pragma unroll
    for (int s = 0; s < SS; s++)
        g_sel[((size_t)(b * SS + s)) * NN + n] = fast_sigmoid(acc[s]);
}

// ============================================================================
// K3: partial[v,b,s,c] = sum_{n in split v} sel[b,s,n] * x[b,c,n]
// ============================================================================
__global__ void __launch_bounds__(256) einsum_kernel(const float* __restrict__ x) {
    __shared__ float ssel[SS][K3CHUNK];

    const int idx  = blockIdx.x;
    const int v    = idx & (NSPLIT - 1);
    const int cblk = (idx >> 2) & 31;
    const int b    = idx >> 7;
    const int tid  = threadIdx.x;
    const int lane = tid & 31;
    const int c    = cblk * 8 + (tid >> 5);

    const int nlo = v * (NN / NSPLIT);
    const float* xc   = x + ((size_t)(b * CC + c)) * NN;
    const float* selb = g_sel + (size_t)b * SS * NN;

    ull acc[SS];
#pragma unroll
    for (int s = 0; s < SS; s++) acc[s] = 0ull;

    for (int n0 = nlo; n0 < nlo + NN / NSPLIT; n0 += K3CHUNK) {
        __syncthreads();
        for (int j = tid; j < SS * K3CHUNK; j += 256) {
            int s  = j >> 9;
            int nn = j & (K3CHUNK - 1);
            ssel[s][nn] = selb[(size_t)s * NN + n0 + nn];
        }
        __syncthreads();

#pragma unroll
        for (int i = 0; i < K3CHUNK / 128; i++) {
            int nl = i * 128 + lane * 4;
            float4 xv = *(const float4*)(xc + n0 + nl);
            ull x01 = pack2(xv.x, xv.y);
            ull x23 = pack2(xv.z, xv.w);
#pragma unroll
            for (int s = 0; s < SS; s++) {
                float4 sv = *(const float4*)(&ssel[s][nl]);
                ffma2(acc[s], pack2(sv.x, sv.y), x01);
                ffma2(acc[s], pack2(sv.z, sv.w), x23);
            }
        }
    }

#pragma unroll
    for (int s = 0; s < SS; s++) {
        float a, bb;
        unpack2(acc[s], a, bb);
        float val = a + bb;
#pragma unroll
        for (int m = 16; m > 0; m >>= 1)
            val += __shfl_xor_sync(0xffffffffu, val, m);
        if (lane == 0)
            g_partial[(((size_t)v * BB + b) * SS + s) * CC + c] = val;
    }
}

// ============================================================================
// K4: out[i] = sum_v partial[v][i] / N
// ============================================================================
__global__ void __launch_bounds__(256) reduce_kernel(float* __restrict__ out) {
    int i = blockIdx.x * 256 + threadIdx.x;
    if (i < BB * SS * CC) {
        float s = 0.f;
#pragma unroll
        for (int v = 0; v < NSPLIT; v++)
            s += g_partial[(size_t)v * (BB * SS * CC) + i];
        out[i] = s * (1.0f / (float)NN);
    }
}

// ============================================================================
extern "C" void kernel_launch(void* const* d_in, const int* in_sizes, int n_in,
                              void* d_out, int out_size) {
    const float* x    = (const float*)d_in[0];   // [8,256,16,32,32]
    const float* Wc   = (const float*)d_in[1];   // [8,256,3,3,3]
    const float* bias = (const float*)d_in[2];   // [8]
    float* out = (float*)d_out;                  // [8,8,256]

    cudaFuncSetAttribute(gemm_kernel,
                         cudaFuncAttributeMaxDynamicSharedMemorySize, GEMM_SMEM);

    prep_kernel<<<BROWS, 256>>>(Wc);
    gemm_kernel<<<BB * (NN / 128), 256, GEMM_SMEM>>>(x);
    shiftadd_kernel<<<(BB * NN) / 256, 256>>>(bias);
    einsum_kernel<<<BB * 32 * NSPLIT, 256>>>(x);
    reduce_kernel<<<(BB * SS * CC + 255) / 256, 256>>>(out);
}

// round 6
// speedup vs baseline: 7.1120x; 1.3597x over previous
#include <cuda_runtime.h>
#include <cuda_bf16.h>
#include <cuda_fp16.h>
#include <cstdint>
#include <cstring>

#define BB   8
#define CC   256
#define DD_  16
#define HH_  32
#define WW_  32
#define SS   8
#define NN   16384
#define PLANE 1024
#define NTAP 27
#define BROWS 224          // padded mo rows (28 tiles of 8)

// GEMM dynamic smem layout (bytes)
#define XH_OFF 0           // 128 rows x 128B (fp16 x tile)
#define BH_OFF 16384       // 224 rows x 128B (W' hi, one kchunk)
#define BL_OFF 45056       // 224 rows x 128B (W' lo)
#define GEMM_SMEM 73728

#define NSPLIT 16
#define K3CHUNK 1024

typedef unsigned int u32;
typedef unsigned long long ull;

// ---------------- scratch ----------------
__device__ __half g_u3[(size_t)BB * NTAP * NN * SS];     // [b][tap][m][s] fp16
__device__ float  g_sel[BB * SS * NN];
__device__ float  g_partial[NSPLIT * BB * SS * CC];
__device__ int4   g_Bh4[4 * BROWS * 8];                  // 4 kchunks x 224 rows x 128B (swizzled)
__device__ int4   g_Bl4[4 * BROWS * 8];

// ---------------- helpers ----------------
__device__ __forceinline__ u32 smem_u32(const void* p) {
    u32 a;
    asm("{ .reg .u64 t; cvta.to.shared.u64 t, %1; cvt.u32.u64 %0, t; }"
        : "=r"(a) : "l"(p));
    return a;
}
__device__ __forceinline__ void ldm4(u32* r, u32 addr) {
    asm volatile("ldmatrix.sync.aligned.m8n8.x4.shared.b16 {%0,%1,%2,%3}, [%4];"
                 : "=r"(r[0]), "=r"(r[1]), "=r"(r[2]), "=r"(r[3]) : "r"(addr));
}
__device__ __forceinline__ void mma16816(float* c, const u32* a, const u32* b) {
    asm volatile("mma.sync.aligned.m16n8k16.row.col.f32.f16.f16.f32 "
                 "{%0,%1,%2,%3}, {%4,%5,%6,%7}, {%8,%9}, {%0,%1,%2,%3};"
                 : "+f"(c[0]), "+f"(c[1]), "+f"(c[2]), "+f"(c[3])
                 : "r"(a[0]), "r"(a[1]), "r"(a[2]), "r"(a[3]),
                   "r"(b[0]), "r"(b[1]));
}
__device__ __forceinline__ ull pack2(float a, float b) {
    ull r; asm("mov.b64 %0, {%1, %2};" : "=l"(r) : "f"(a), "f"(b)); return r;
}
__device__ __forceinline__ void unpack2(ull v, float& a, float& b) {
    asm("mov.b64 {%0, %1}, %2;" : "=f"(a), "=f"(b) : "l"(v));
}
__device__ __forceinline__ void ffma2(ull& d, ull a, ull b) {
    asm("fma.rn.f32x2 %0, %1, %2, %0;" : "+l"(d) : "l"(a), "l"(b));
}
__device__ __forceinline__ float fast_sigmoid(float v) {
    return 1.0f / (1.0f + __expf(-v));
}

// ============================================================================
// K0: prep W' -> fp16 hi/lo SW128-swizzled smem images per kchunk.
// grid = 224 (mo rows incl. pad), block = 256 (c).
// ============================================================================
__global__ void __launch_bounds__(256) prep_kernel(const float* __restrict__ Wc) {
    const int mo = blockIdx.x;
    const int c  = threadIdx.x;
    float w = 0.0f;
    if (mo < 216) {
        int s = mo & 7, tap = mo >> 3;
        w = Wc[((size_t)s * CC + c) * 27 + tap];
    }
    __half h = __float2half_rn(w);
    float r = w - __half2float(h);
    __half l = __float2half_rn(r);

    const int kc = c >> 6;
    const u32 kb = (u32)((c & 63) * 2) ^ (u32)((mo & 7) << 4);  // SW128 within row
    const size_t idx = (size_t)kc * (BROWS * 64) + ((u32)mo * 128 + kb) / 2;
    unsigned short hb, lb;
    memcpy(&hb, &h, 2); memcpy(&lb, &l, 2);
    ((unsigned short*)g_Bh4)[idx] = hb;
    ((unsigned short*)g_Bl4)[idx] = lb;
}

// ============================================================================
// K1: GEMM u[m][mo] = sum_k x[k][m] * W'[mo][k]  via mma.sync fp16 two-split
//   (x in fp16; W' = Wh + Wl fp16; u = x*Wh + x*Wl, A fragments shared)
// grid = B*128 = 1024 CTAs, block = 256 (8 warps = 4 m-groups x 2 n-halves).
// ============================================================================
__global__ void __launch_bounds__(256) gemm_kernel(const float* __restrict__ x) {
    extern __shared__ char smem[];
    const u32 sb = smem_u32(smem);
    const int tid = threadIdx.x, lane = tid & 31, warp = tid >> 5;
    const int mg = warp & 3, nh = warp >> 2;
    const int b  = blockIdx.x >> 7;
    const int n0 = (blockIdx.x & 127) * 128;

    float acc[7][2][2][4];
#pragma unroll
    for (int p = 0; p < 7; p++)
#pragma unroll
        for (int t = 0; t < 2; t++)
#pragma unroll
            for (int m = 0; m < 2; m++)
#pragma unroll
                for (int i = 0; i < 4; i++) acc[p][t][m][i] = 0.0f;

    const u32 xm     = (u32)(lane & 7) << 4;
    const int arow   = (lane & 7) + ((lane >> 3) & 1) * 8;
    const u32 a_ksel = (u32)((lane >> 4) & 1) * 16;
    const u32 b_ksel = (u32)((lane >> 3) & 1) * 16;
    const int btile  = (lane >> 4);
    const int brow   = lane & 7;

    const int mt0 = mg * 32;
    const u32 aXh0 = sb + XH_OFF + (u32)(mt0 + arow) * 128;
    const u32 aXh1 = aXh0 + 16 * 128;

    const float* xb = x + (size_t)b * CC * NN + n0;
    const int cm  = tid & 127;
    const int ckh = tid >> 7;
    const u32 cxm = (u32)(cm & 7) << 4;

#pragma unroll 1
    for (int kc = 0; kc < 4; kc++) {
        __syncthreads();
        // ---- copy W' kchunk images (pre-swizzled) ----
        {
            const int4* srcH = g_Bh4 + kc * (BROWS * 8);
            const int4* srcL = g_Bl4 + kc * (BROWS * 8);
            int4* dH = (int4*)(smem + BH_OFF);
            int4* dL = (int4*)(smem + BL_OFF);
#pragma unroll
            for (int i = 0; i < 7; i++) {
                dH[tid + i * 256] = srcH[tid + i * 256];
                dL[tid + i * 256] = srcL[tid + i * 256];
            }
        }
        // ---- load x (coalesced), fp16 convert, swizzled smem stores ----
        {
            const float* xp = xb + (size_t)(kc * 64 + ckh * 32) * NN + cm;
#pragma unroll
            for (int u = 0; u < 16; u++) {
                float v0 = xp[(size_t)(2 * u) * NN];
                float v1 = xp[(size_t)(2 * u + 1) * NN];
                __half2 h2 = __floats2half2_rn(v0, v1);
                u32 hp;
                memcpy(&hp, &h2, 4);
                u32 kb = (u32)(ckh * 64 + u * 4) ^ cxm;
                *(u32*)(smem + XH_OFF + cm * 128 + kb) = hp;
            }
        }
        __syncthreads();

        // ---- 4 k16 steps ----
#pragma unroll
        for (int j = 0; j < 4; j++) {
            const u32 ka  = ((u32)(j * 32) + a_ksel) ^ xm;
            const u32 kb2 = ((u32)(j * 32) + b_ksel) ^ xm;
            u32 Ah0[4], Ah1[4];
            ldm4(Ah0, aXh0 + ka); ldm4(Ah1, aXh1 + ka);
#pragma unroll
            for (int p = 0; p < 7; p++) {
                const int tile = nh * 14 + 2 * p + btile;
                const u32 boff = (u32)(tile * 8 + brow) * 128 + kb2;
                u32 BfH[4], BfL[4];
                ldm4(BfH, sb + BH_OFF + boff);
                mma16816(acc[p][0][0], Ah0, BfH);
                mma16816(acc[p][0][1], Ah1, BfH);
                mma16816(acc[p][1][0], Ah0, BfH + 2);
                mma16816(acc[p][1][1], Ah1, BfH + 2);
                ldm4(BfL, sb + BL_OFF + boff);
                mma16816(acc[p][0][0], Ah0, BfL);
                mma16816(acc[p][0][1], Ah1, BfL);
                mma16816(acc[p][1][0], Ah0, BfL + 2);
                mma16816(acc[p][1][1], Ah1, BfL + 2);
            }
        }
    }

    // ---- epilogue: fp16 stores, fully coalesced (tile == tap) ----
    const int mrow = lane >> 2;
    const int q    = lane & 3;
    u32* up = (u32*)g_u3;
#pragma unroll
    for (int p = 0; p < 7; p++)
#pragma unroll
        for (int tt = 0; tt < 2; tt++) {
            const int tile = nh * 14 + 2 * p + tt;
            if (tile >= NTAP) continue;
#pragma unroll
            for (int mi = 0; mi < 2; mi++) {
                const float* cf = acc[p][tt][mi];
                const int m = n0 + mt0 + mi * 16 + mrow;
                const size_t base = ((size_t)(b * NTAP + tile) * NN + m) * 4 + q;
                __half2 h01 = __floats2half2_rn(cf[0], cf[1]);
                __half2 h23 = __floats2half2_rn(cf[2], cf[3]);
                u32 w01, w23;
                memcpy(&w01, &h01, 4); memcpy(&w23, &h23, 4);
                up[base]      = w01;
                up[base + 32] = w23;
            }
        }
}

// ============================================================================
// K2: shift-add taps + bias + sigmoid -> g_sel
// ============================================================================
__global__ void __launch_bounds__(256) shiftadd_kernel(const float* __restrict__ bias) {
    const int gi = blockIdx.x * 256 + threadIdx.x;
    const int b = gi >> 14, n = gi & (NN - 1);
    const int d = n >> 10, h = (n >> 5) & 31, w = n & 31;

    float acc[SS];
#pragma unroll
    for (int s = 0; s < SS; s++) acc[s] = bias[s];

    const uint4* ub = (const uint4*)g_u3 + (size_t)b * NTAP * NN;

#pragma unroll
    for (int kd = 0; kd < 3; kd++) {
        const int dd = d + kd - 1;
        if ((unsigned)dd >= (unsigned)DD_) continue;
#pragma unroll
        for (int kh = 0; kh < 3; kh++) {
            const int hh = h + kh - 1;
            if ((unsigned)hh >= (unsigned)HH_) continue;
#pragma unroll
            for (int kw = 0; kw < 3; kw++) {
                const int ww = w + kw - 1;
                if ((unsigned)ww >= (unsigned)WW_) continue;
                const int tap = (kd * 3 + kh) * 3 + kw;
                const int m = dd * PLANE + hh * WW_ + ww;
                uint4 v = ub[(size_t)tap * NN + m];
                __half2 p0, p1, p2, p3;
                memcpy(&p0, &v.x, 4); memcpy(&p1, &v.y, 4);
                memcpy(&p2, &v.z, 4); memcpy(&p3, &v.w, 4);
                float2 f0 = __half22float2(p0), f1 = __half22float2(p1);
                float2 f2 = __half22float2(p2), f3 = __half22float2(p3);
                acc[0] += f0.x; acc[1] += f0.y; acc[2] += f1.x; acc[3] += f1.y;
                acc[4] += f2.x; acc[5] += f2.y; acc[6] += f3.x; acc[7] += f3.y;
            }
        }
    }
#pragma unroll
    for (int s = 0; s < SS; s++)
        g_sel[((size_t)(b * SS + s)) * NN + n] = fast_sigmoid(acc[s]);
}

// ============================================================================
// K3: partial[v,b,s,c] = sum_{n in split v} sel[b,s,n] * x[b,c,n]
// grid = B*8*16 = 1024, block 256 (8 warps x 4 channels each).
// ============================================================================
__global__ void __launch_bounds__(256, 2) einsum_kernel(const float* __restrict__ x) {
    __shared__ float ssel[SS][K3CHUNK];    // 32 KB

    const int idx  = blockIdx.x;
    const int v    = idx & 15;
    const int cblk = (idx >> 4) & 7;
    const int b    = idx >> 7;
    const int tid  = threadIdx.x;
    const int lane = tid & 31;
    const int warp = tid >> 5;
    const int c0   = cblk * 32 + warp * 4;

    const int n0 = v * K3CHUNK;
    const float* xc   = x + ((size_t)(b * CC + c0)) * NN + n0;
    const float* selb = g_sel + (size_t)b * SS * NN + n0;

    ull acc[4][SS];
#pragma unroll
    for (int cc = 0; cc < 4; cc++)
#pragma unroll
        for (int s = 0; s < SS; s++) acc[cc][s] = 0ull;

    // stage sel chunk (8 x 1024 floats)
    {
        const int4* src = (const int4*)selb;
        for (int j = tid; j < SS * (K3CHUNK / 4); j += 256) {
            int s  = j >> 8;                  // 256 int4 per s-row
            int c4 = j & 255;
            *(int4*)&ssel[s][c4 * 4] = src[(size_t)s * (NN / 4) + c4];
        }
    }
    __syncthreads();

#pragma unroll 2
    for (int i = 0; i < K3CHUNK / 128; i++) {
        const int nl = i * 128 + lane * 4;
        ull x01[4], x23[4];
#pragma unroll
        for (int cc = 0; cc < 4; cc++) {
            float4 xv = *(const float4*)(xc + (size_t)cc * NN + nl);
            x01[cc] = pack2(xv.x, xv.y);
            x23[cc] = pack2(xv.z, xv.w);
        }
#pragma unroll
        for (int s = 0; s < SS; s++) {
            float4 sv = *(const float4*)(&ssel[s][nl]);
            ull s01 = pack2(sv.x, sv.y);
            ull s23 = pack2(sv.z, sv.w);
#pragma unroll
            for (int cc = 0; cc < 4; cc++) {
                ffma2(acc[cc][s], s01, x01[cc]);
                ffma2(acc[cc][s], s23, x23[cc]);
            }
        }
    }

#pragma unroll
    for (int cc = 0; cc < 4; cc++)
#pragma unroll
        for (int s = 0; s < SS; s++) {
            float a, bb;
            unpack2(acc[cc][s], a, bb);
            float val = a + bb;
#pragma unroll
            for (int m = 16; m > 0; m >>= 1)
                val += __shfl_xor_sync(0xffffffffu, val, m);
            if (lane == 0)
                g_partial[(((size_t)v * BB + b) * SS + s) * CC + c0 + cc] = val;
        }
}

// ============================================================================
// K4: out[i] = sum_v partial[v][i] / N
// ============================================================================
__global__ void __launch_bounds__(256) reduce_kernel(float* __restrict__ out) {
    int i = blockIdx.x * 256 + threadIdx.x;
    if (i < BB * SS * CC) {
        float s = 0.f;
#pragma unroll
        for (int v = 0; v < NSPLIT; v++)
            s += g_partial[(size_t)v * (BB * SS * CC) + i];
        out[i] = s * (1.0f / (float)NN);
    }
}

// ============================================================================
extern "C" void kernel_launch(void* const* d_in, const int* in_sizes, int n_in,
                              void* d_out, int out_size) {
    const float* x    = (const float*)d_in[0];   // [8,256,16,32,32]
    const float* Wc   = (const float*)d_in[1];   // [8,256,3,3,3]
    const float* bias = (const float*)d_in[2];   // [8]
    float* out = (float*)d_out;                  // [8,8,256]

    cudaFuncSetAttribute(gemm_kernel,
                         cudaFuncAttributeMaxDynamicSharedMemorySize, GEMM_SMEM);

    prep_kernel<<<BROWS, 256>>>(Wc);
    gemm_kernel<<<BB * (NN / 128), 256, GEMM_SMEM>>>(x);
    shiftadd_kernel<<<(BB * NN) / 256, 256>>>(bias);
    einsum_kernel<<<BB * 8 * NSPLIT, 256>>>(x);
    reduce_kernel<<<(BB * SS * CC + 255) / 256, 256>>>(out);
}

// round 7
// speedup vs baseline: 8.4008x; 1.1812x over previous
#include <cuda_runtime.h>
#include <cuda_fp16.h>
#include <cstdint>
#include <cstring>

#define BB   8
#define CC   256
#define DD_  16
#define HH_  32
#define WW_  32
#define SS   8
#define NN   16384
#define PLANE 1024
#define NTAP 27
#define BROWS 224          // padded mo rows (28 tiles of 8)

// GEMM dynamic smem layout (bytes)
#define XH_OFF 0           // 128 rows x 128B (fp16 x tile)
#define BH_OFF 16384       // 224 rows x 128B (W' fp16, one kchunk)
#define GEMM_SMEM 45056

#define NSPLIT 16
#define K3CHUNK 1024

typedef unsigned int u32;
typedef unsigned long long ull;

// ---------------- scratch ----------------
__device__ __half g_u3[(size_t)BB * NTAP * NN * SS];     // [b][tap][m][s] fp16
__device__ u32    g_xh2[(size_t)BB * (CC / 2) * NN];     // [b][cpair][n], u32 = (c,c+1) fp16
__device__ float  g_sel[BB * SS * NN];
__device__ float  g_partial[NSPLIT * BB * SS * CC];
__device__ int4   g_Bh4[4 * BROWS * 8];                  // 4 kchunks x 224 rows x 128B (swizzled)

// ---------------- helpers ----------------
__device__ __forceinline__ u32 smem_u32(const void* p) {
    u32 a;
    asm("{ .reg .u64 t; cvta.to.shared.u64 t, %1; cvt.u32.u64 %0, t; }"
        : "=r"(a) : "l"(p));
    return a;
}
__device__ __forceinline__ void ldm4(u32* r, u32 addr) {
    asm volatile("ldmatrix.sync.aligned.m8n8.x4.shared.b16 {%0,%1,%2,%3}, [%4];"
                 : "=r"(r[0]), "=r"(r[1]), "=r"(r[2]), "=r"(r[3]) : "r"(addr));
}
__device__ __forceinline__ void mma16816(float* c, const u32* a, const u32* b) {
    asm volatile("mma.sync.aligned.m16n8k16.row.col.f32.f16.f16.f32 "
                 "{%0,%1,%2,%3}, {%4,%5,%6,%7}, {%8,%9}, {%0,%1,%2,%3};"
                 : "+f"(c[0]), "+f"(c[1]), "+f"(c[2]), "+f"(c[3])
                 : "r"(a[0]), "r"(a[1]), "r"(a[2]), "r"(a[3]),
                   "r"(b[0]), "r"(b[1]));
}
__device__ __forceinline__ ull pack2(float a, float b) {
    ull r; asm("mov.b64 %0, {%1, %2};" : "=l"(r) : "f"(a), "f"(b)); return r;
}
__device__ __forceinline__ void unpack2(ull v, float& a, float& b) {
    asm("mov.b64 {%0, %1}, %2;" : "=f"(a), "=f"(b) : "l"(v));
}
__device__ __forceinline__ void ffma2(ull& d, ull a, ull b) {
    asm("fma.rn.f32x2 %0, %1, %2, %0;" : "+l"(d) : "l"(a), "l"(b));
}
__device__ __forceinline__ float fast_sigmoid(float v) {
    return 1.0f / (1.0f + __expf(-v));
}

// ============================================================================
// K0: prep W' -> fp16 SW128-swizzled smem image per kchunk.
// grid = 224 (mo rows incl. pad), block = 256 (c).
// ============================================================================
__global__ void __launch_bounds__(256) prep_kernel(const float* __restrict__ Wc) {
    const int mo = blockIdx.x;
    const int c  = threadIdx.x;
    float w = 0.0f;
    if (mo < 216) {
        int s = mo & 7, tap = mo >> 3;
        w = Wc[((size_t)s * CC + c) * 27 + tap];
    }
    __half h = __float2half_rn(w);

    const int kc = c >> 6;
    const u32 kb = (u32)((c & 63) * 2) ^ (u32)((mo & 7) << 4);  // SW128 within row
    const size_t idx = (size_t)kc * (BROWS * 64) + ((u32)mo * 128 + kb) / 2;
    unsigned short hb;
    memcpy(&hb, &h, 2);
    ((unsigned short*)g_Bh4)[idx] = hb;
}

// ============================================================================
// K1: GEMM u[m][mo] = sum_k x[k][m] * W'[mo][k]  via mma.sync fp16
// grid = B*128 = 1024 CTAs, block = 256 (8 warps = 4 m-groups x 2 n-halves).
// Side product: fp16 x dumped to g_xh2 [b][cpair][n] for the einsum.
// ============================================================================
__global__ void __launch_bounds__(256) gemm_kernel(const float* __restrict__ x) {
    extern __shared__ char smem[];
    const u32 sb = smem_u32(smem);
    const int tid = threadIdx.x, lane = tid & 31, warp = tid >> 5;
    const int mg = warp & 3, nh = warp >> 2;
    const int b  = blockIdx.x >> 7;
    const int n0 = (blockIdx.x & 127) * 128;

    float acc[7][2][2][4];
#pragma unroll
    for (int p = 0; p < 7; p++)
#pragma unroll
        for (int t = 0; t < 2; t++)
#pragma unroll
            for (int m = 0; m < 2; m++)
#pragma unroll
                for (int i = 0; i < 4; i++) acc[p][t][m][i] = 0.0f;

    const u32 xm     = (u32)(lane & 7) << 4;
    const int arow   = (lane & 7) + ((lane >> 3) & 1) * 8;
    const u32 a_ksel = (u32)((lane >> 4) & 1) * 16;
    const u32 b_ksel = (u32)((lane >> 3) & 1) * 16;
    const int btile  = (lane >> 4);
    const int brow   = lane & 7;

    const int mt0 = mg * 32;
    const u32 aXh0 = sb + XH_OFF + (u32)(mt0 + arow) * 128;
    const u32 aXh1 = aXh0 + 16 * 128;

    const float* xb = x + (size_t)b * CC * NN + n0;
    const int cm  = tid & 127;        // conversion: m row (lane == m%32)
    const int ckh = tid >> 7;         // conversion: k half of chunk (32 k)
    const u32 cxm = (u32)(cm & 7) << 4;
    u32* xh_out = g_xh2 + (size_t)b * (CC / 2) * NN + n0 + cm;

#pragma unroll 1
    for (int kc = 0; kc < 4; kc++) {
        __syncthreads();
        // ---- copy W' kchunk image (pre-swizzled) ----
        {
            const int4* srcH = g_Bh4 + kc * (BROWS * 8);
            int4* dH = (int4*)(smem + BH_OFF);
#pragma unroll
            for (int i = 0; i < 7; i++)
                dH[tid + i * 256] = srcH[tid + i * 256];
        }
        // ---- load x (coalesced), fp16 convert, smem + global dumps ----
        {
            const float* xp = xb + (size_t)(kc * 64 + ckh * 32) * NN + cm;
            u32 hp[16];
#pragma unroll
            for (int u = 0; u < 16; u++) {
                float v0 = xp[(size_t)(2 * u) * NN];
                float v1 = xp[(size_t)(2 * u + 1) * NN];
                __half2 h2 = __floats2half2_rn(v0, v1);
                memcpy(&hp[u], &h2, 4);
            }
            // smem: 4 x STS.128, conflict-free (lane = m % 32)
#pragma unroll
            for (int j = 0; j < 4; j++) {
                u32 off = ((u32)(ckh * 64 + j * 16)) ^ cxm;
                uint4 v4 = make_uint4(hp[4 * j], hp[4 * j + 1],
                                      hp[4 * j + 2], hp[4 * j + 3]);
                *(uint4*)(smem + XH_OFF + cm * 128 + off) = v4;
            }
            // global: coalesced STG.32, layout [b][cpair][n]
            u32* xo = xh_out + (size_t)(kc * 32 + ckh * 16) * NN;
#pragma unroll
            for (int u = 0; u < 16; u++)
                xo[(size_t)u * NN] = hp[u];
        }
        __syncthreads();

        // ---- 4 k16 steps ----
#pragma unroll
        for (int j = 0; j < 4; j++) {
            const u32 ka  = ((u32)(j * 32) + a_ksel) ^ xm;
            const u32 kb2 = ((u32)(j * 32) + b_ksel) ^ xm;
            u32 Ah0[4], Ah1[4];
            ldm4(Ah0, aXh0 + ka); ldm4(Ah1, aXh1 + ka);
#pragma unroll
            for (int p = 0; p < 7; p++) {
                const int tile = nh * 14 + 2 * p + btile;
                const u32 boff = (u32)(tile * 8 + brow) * 128 + kb2;
                u32 Bf[4];
                ldm4(Bf, sb + BH_OFF + boff);
                mma16816(acc[p][0][0], Ah0, Bf);
                mma16816(acc[p][0][1], Ah1, Bf);
                mma16816(acc[p][1][0], Ah0, Bf + 2);
                mma16816(acc[p][1][1], Ah1, Bf + 2);
            }
        }
    }

    // ---- epilogue: fp16 stores, fully coalesced (tile == tap) ----
    const int mrow = lane >> 2;
    const int q    = lane & 3;
    u32* up = (u32*)g_u3;
#pragma unroll
    for (int p = 0; p < 7; p++)
#pragma unroll
        for (int tt = 0; tt < 2; tt++) {
            const int tile = nh * 14 + 2 * p + tt;
            if (tile >= NTAP) continue;
#pragma unroll
            for (int mi = 0; mi < 2; mi++) {
                const float* cf = acc[p][tt][mi];
                const int m = n0 + mt0 + mi * 16 + mrow;
                const size_t base = ((size_t)(b * NTAP + tile) * NN + m) * 4 + q;
                __half2 h01 = __floats2half2_rn(cf[0], cf[1]);
                __half2 h23 = __floats2half2_rn(cf[2], cf[3]);
                u32 w01, w23;
                memcpy(&w01, &h01, 4); memcpy(&w23, &h23, 4);
                up[base]      = w01;
                up[base + 32] = w23;
            }
        }
}

// ============================================================================
// K2: shift-add taps + bias + sigmoid -> g_sel
// ============================================================================
__global__ void __launch_bounds__(256) shiftadd_kernel(const float* __restrict__ bias) {
    const int gi = blockIdx.x * 256 + threadIdx.x;
    const int b = gi >> 14, n = gi & (NN - 1);
    const int d = n >> 10, h = (n >> 5) & 31, w = n & 31;

    float acc[SS];
#pragma unroll
    for (int s = 0; s < SS; s++) acc[s] = bias[s];

    const uint4* ub = (const uint4*)g_u3 + (size_t)b * NTAP * NN;

#pragma unroll
    for (int kd = 0; kd < 3; kd++) {
        const int dd = d + kd - 1;
        if ((unsigned)dd >= (unsigned)DD_) continue;
#pragma unroll
        for (int kh = 0; kh < 3; kh++) {
            const int hh = h + kh - 1;
            if ((unsigned)hh >= (unsigned)HH_) continue;
#pragma unroll
            for (int kw = 0; kw < 3; kw++) {
                const int ww = w + kw - 1;
                if ((unsigned)ww >= (unsigned)WW_) continue;
                const int tap = (kd * 3 + kh) * 3 + kw;
                const int m = dd * PLANE + hh * WW_ + ww;
                uint4 v = ub[(size_t)tap * NN + m];
                __half2 p0, p1, p2, p3;
                memcpy(&p0, &v.x, 4); memcpy(&p1, &v.y, 4);
                memcpy(&p2, &v.z, 4); memcpy(&p3, &v.w, 4);
                float2 f0 = __half22float2(p0), f1 = __half22float2(p1);
                float2 f2 = __half22float2(p2), f3 = __half22float2(p3);
                acc[0] += f0.x; acc[1] += f0.y; acc[2] += f1.x; acc[3] += f1.y;
                acc[4] += f2.x; acc[5] += f2.y; acc[6] += f3.x; acc[7] += f3.y;
            }
        }
    }
#pragma unroll
    for (int s = 0; s < SS; s++)
        g_sel[((size_t)(b * SS + s)) * NN + n] = fast_sigmoid(acc[s]);
}

// ============================================================================
// K3: partial[v,b,s,c] = sum_{n in split v} sel[b,s,n] * xh[c][n]
// grid = B*8*16 = 1024, block 256 (8 warps x 4 channels each).
// x read as fp16 channel pairs from g_xh2.
// ============================================================================
__global__ void __launch_bounds__(256, 2) einsum_kernel() {
    __shared__ float ssel[SS][K3CHUNK];    // 32 KB

    const int idx  = blockIdx.x;
    const int v    = idx & 15;
    const int cblk = (idx >> 4) & 7;
    const int b    = idx >> 7;
    const int tid  = threadIdx.x;
    const int lane = tid & 31;
    const int warp = tid >> 5;
    const int c0   = cblk * 32 + warp * 4;
    const int cp0  = c0 >> 1;              // channel-pair index (even)

    const int n0 = v * K3CHUNK;
    const u32* xp = g_xh2 + (size_t)(b * (CC / 2) + cp0) * NN + n0;
    const float* selb = g_sel + (size_t)b * SS * NN + n0;

    ull acc[4][SS];
#pragma unroll
    for (int cc = 0; cc < 4; cc++)
#pragma unroll
        for (int s = 0; s < SS; s++) acc[cc][s] = 0ull;

    // stage sel chunk (8 x 1024 floats)
    {
        const int4* src = (const int4*)selb;
        for (int j = tid; j < SS * (K3CHUNK / 4); j += 256) {
            int s  = j >> 8;
            int c4 = j & 255;
            *(int4*)&ssel[s][c4 * 4] = src[(size_t)s * (NN / 4) + c4];
        }
    }
    __syncthreads();

#pragma unroll 2
    for (int i = 0; i < K3CHUNK / 128; i++) {
        const int nl = i * 128 + lane * 4;
        // two channel-pairs, 4 n each: 2 x LDG.128
        ull xe[2][2], xo[2][2];
#pragma unroll
        for (int cp = 0; cp < 2; cp++) {
            uint4 v4 = *(const uint4*)(xp + (size_t)cp * NN + nl);
            __half2 h0, h1, h2, h3;
            memcpy(&h0, &v4.x, 4); memcpy(&h1, &v4.y, 4);
            memcpy(&h2, &v4.z, 4); memcpy(&h3, &v4.w, 4);
            float2 f0 = __half22float2(h0), f1 = __half22float2(h1);
            float2 f2 = __half22float2(h2), f3 = __half22float2(h3);
            xe[cp][0] = pack2(f0.x, f1.x);   // even channel, n(0,1)
            xe[cp][1] = pack2(f2.x, f3.x);   // even channel, n(2,3)
            xo[cp][0] = pack2(f0.y, f1.y);   // odd channel
            xo[cp][1] = pack2(f2.y, f3.y);
        }
#pragma unroll
        for (int s = 0; s < SS; s++) {
            float4 sv = *(const float4*)(&ssel[s][nl]);
            ull s01 = pack2(sv.x, sv.y);
            ull s23 = pack2(sv.z, sv.w);
            ffma2(acc[0][s], s01, xe[0][0]); ffma2(acc[0][s], s23, xe[0][1]);
            ffma2(acc[1][s], s01, xo[0][0]); ffma2(acc[1][s], s23, xo[0][1]);
            ffma2(acc[2][s], s01, xe[1][0]); ffma2(acc[2][s], s23, xe[1][1]);
            ffma2(acc[3][s], s01, xo[1][0]); ffma2(acc[3][s], s23, xo[1][1]);
        }
    }

#pragma unroll
    for (int cc = 0; cc < 4; cc++)
#pragma unroll
        for (int s = 0; s < SS; s++) {
            float a, bb;
            unpack2(acc[cc][s], a, bb);
            float val = a + bb;
#pragma unroll
            for (int m = 16; m > 0; m >>= 1)
                val += __shfl_xor_sync(0xffffffffu, val, m);
            if (lane == 0)
                g_partial[(((size_t)v * BB + b) * SS + s) * CC + c0 + cc] = val;
        }
}

// ============================================================================
// K4: out[i] = sum_v partial[v][i] / N
// ============================================================================
__global__ void __launch_bounds__(256) reduce_kernel(float* __restrict__ out) {
    int i = blockIdx.x * 256 + threadIdx.x;
    if (i < BB * SS * CC) {
        float s = 0.f;
#pragma unroll
        for (int v = 0; v < NSPLIT; v++)
            s += g_partial[(size_t)v * (BB * SS * CC) + i];
        out[i] = s * (1.0f / (float)NN);
    }
}

// ============================================================================
extern "C" void kernel_launch(void* const* d_in, const int* in_sizes, int n_in,
                              void* d_out, int out_size) {
    const float* x    = (const float*)d_in[0];   // [8,256,16,32,32]
    const float* Wc   = (const float*)d_in[1];   // [8,256,3,3,3]
    const float* bias = (const float*)d_in[2];   // [8]
    float* out = (float*)d_out;                  // [8,8,256]

    cudaFuncSetAttribute(gemm_kernel,
                         cudaFuncAttributeMaxDynamicSharedMemorySize, GEMM_SMEM);

    prep_kernel<<<BROWS, 256>>>(Wc);
    gemm_kernel<<<BB * (NN / 128), 256, GEMM_SMEM>>>(x);
    shiftadd_kernel<<<(BB * NN) / 256, 256>>>(bias);
    einsum_kernel<<<BB * 8 * NSPLIT, 256>>>();
    reduce_kernel<<<(BB * SS * CC + 255) / 256, 256>>>(out);
}

// round 9
// speedup vs baseline: 10.9056x; 1.2982x over previous
#include <cuda_runtime.h>
#include <cuda_fp16.h>
#include <cstdint>
#include <cstring>

#define BB   8
#define CC   256
#define DD_  16
#define HH_  32
#define WW_  32
#define SS   8
#define NN   16384
#define PLANE 1024
#define NTAP 27
#define BROWS 224            // padded mo rows (28 tiles of 8)
#define B_IMG 28672          // bytes per kchunk W' image

// GEMM smem offsets (bytes)
#define XF0_OFF 0            // fp32 x chunk buf0: 64c x 128n x 4B = 32KB
#define XF1_OFF 32768
#define XH_OFF  65536        // fp16 swizzled x tile: 128 rows x 128B
#define B0_OFF  81920
#define B1_OFF  110592
#define GEMM_SMEM 139264

// einsum
#define NK 16
#define KW 64
#define XST 72               // halfs per x row (144B, conflict-free ldmatrix)
#define SELST 72
// dynamic smem layout (halfs): sx[2][256*XST] then ssel[2][16*SELST]
#define E_SX_HALFS   (256 * XST)          // per buffer
#define E_SEL_HALFS  (16 * SELST)
#define E_SEL_BASE   (2 * E_SX_HALFS)     // half-index where ssel starts
#define EINSUM_SMEM  ((2 * E_SX_HALFS + 2 * E_SEL_HALFS) * 2)   // 78336 bytes

typedef unsigned int u32;
typedef unsigned long long ull;

// ---------------- scratch ----------------
__device__ __half g_u3[(size_t)BB * NTAP * NN * SS];   // [b][tap][m][s]
__device__ u32    g_xh2[(size_t)BB * (CC / 2) * NN];   // [b][cpair][n] fp16 pairs
__device__ __half g_selh[(size_t)BB * SS * NN];        // [b][s][n] fp16
__device__ float  g_partial[NK * BB * SS * CC];
__device__ int4   g_Bh4[4 * BROWS * 8];                // 4 kchunks x 224 rows x 128B

// ---------------- helpers ----------------
__device__ __forceinline__ u32 smem_u32(const void* p) {
    u32 a;
    asm("{ .reg .u64 t; cvta.to.shared.u64 t, %1; cvt.u32.u64 %0, t; }"
        : "=r"(a) : "l"(p));
    return a;
}
__device__ __forceinline__ void ldm4(u32* r, u32 addr) {
    asm volatile("ldmatrix.sync.aligned.m8n8.x4.shared.b16 {%0,%1,%2,%3}, [%4];"
                 : "=r"(r[0]), "=r"(r[1]), "=r"(r[2]), "=r"(r[3]) : "r"(addr));
}
__device__ __forceinline__ void ldm2(u32* r, u32 addr) {
    asm volatile("ldmatrix.sync.aligned.m8n8.x2.shared.b16 {%0,%1}, [%2];"
                 : "=r"(r[0]), "=r"(r[1]) : "r"(addr));
}
__device__ __forceinline__ void mma16816(float* c, const u32* a, const u32* b) {
    asm volatile("mma.sync.aligned.m16n8k16.row.col.f32.f16.f16.f32 "
                 "{%0,%1,%2,%3}, {%4,%5,%6,%7}, {%8,%9}, {%0,%1,%2,%3};"
                 : "+f"(c[0]), "+f"(c[1]), "+f"(c[2]), "+f"(c[3])
                 : "r"(a[0]), "r"(a[1]), "r"(a[2]), "r"(a[3]),
                   "r"(b[0]), "r"(b[1]));
}
__device__ __forceinline__ void cp_async16(u32 dst, const void* src) {
    asm volatile("cp.async.cg.shared.global [%0], [%1], 16;"
                 :: "r"(dst), "l"(src) : "memory");
}
#define CP_COMMIT() asm volatile("cp.async.commit_group;" ::: "memory")
#define CP_WAIT0()  asm volatile("cp.async.wait_group 0;" ::: "memory")

__device__ __forceinline__ float fast_sigmoid(float v) {
    return 1.0f / (1.0f + __expf(-v));
}

// ============================================================================
// K0: prep W' -> fp16 SW128-swizzled smem image per kchunk.
// ============================================================================
__global__ void __launch_bounds__(256) prep_kernel(const float* __restrict__ Wc) {
    const int mo = blockIdx.x;
    const int c  = threadIdx.x;
    float w = 0.0f;
    if (mo < 216) {
        int s = mo & 7, tap = mo >> 3;
        w = Wc[((size_t)s * CC + c) * 27 + tap];
    }
    __half h = __float2half_rn(w);
    const int kc = c >> 6;
    const u32 kb = (u32)((c & 63) * 2) ^ (u32)((mo & 7) << 4);
    const size_t idx = (size_t)kc * (BROWS * 64) + ((u32)mo * 128 + kb) / 2;
    unsigned short hb;
    memcpy(&hb, &h, 2);
    ((unsigned short*)g_Bh4)[idx] = hb;
}

// ============================================================================
// K1: GEMM u[m][mo] = sum_k x[k][m] * W'[mo][k], cp.async double-buffered.
// grid = B*128, block 256 (8 warps = 4 m-groups x 2 n-halves).
// ============================================================================
__global__ void __launch_bounds__(256) gemm_kernel(const float* __restrict__ x) {
    extern __shared__ char smem[];
    const u32 sb = smem_u32(smem);
    const int tid = threadIdx.x, lane = tid & 31, warp = tid >> 5;
    const int mg = warp & 3, nh = warp >> 2;
    const int b  = blockIdx.x >> 7;
    const int n0 = (blockIdx.x & 127) * 128;

    float acc[7][2][2][4];
#pragma unroll
    for (int p = 0; p < 7; p++)
#pragma unroll
        for (int t = 0; t < 2; t++)
#pragma unroll
            for (int m = 0; m < 2; m++)
#pragma unroll
                for (int i = 0; i < 4; i++) acc[p][t][m][i] = 0.0f;

    const u32 xm     = (u32)(lane & 7) << 4;
    const int arow   = (lane & 7) + ((lane >> 3) & 1) * 8;
    const u32 a_ksel = (u32)((lane >> 4) & 1) * 16;
    const u32 b_ksel = (u32)((lane >> 3) & 1) * 16;
    const int btile  = (lane >> 4);
    const int brow   = lane & 7;

    const int mt0 = mg * 32;
    const u32 aXh0 = sb + XH_OFF + (u32)(mt0 + arow) * 128;
    const u32 aXh1 = aXh0 + 16 * 128;

    const float* xg = x + (size_t)b * CC * NN + n0;
    const int cm  = tid & 127;
    const int ckh = tid >> 7;
    const u32 cxm = (u32)(cm & 7) << 4;
    u32* xh_out = g_xh2 + (size_t)b * (CC / 2) * NN + n0 + cm;

    auto fill_x = [&](int kc) {
        const u32 dst = sb + (u32)((kc & 1) ? XF1_OFF : XF0_OFF);
#pragma unroll
        for (int p = 0; p < 8; p++) {
            int u = tid + p * 256;
            int row = u >> 5, col = u & 31;
            cp_async16(dst + (u32)row * 512 + (u32)col * 16,
                       xg + (size_t)(kc * 64 + row) * NN + col * 4);
        }
    };
    auto fill_B = [&](int kc) {
        const u32 dst = sb + (u32)((kc & 1) ? B1_OFF : B0_OFF);
        const char* src = ((const char*)g_Bh4) + (size_t)kc * B_IMG;
#pragma unroll
        for (int p = 0; p < 7; p++) {
            int u = tid + p * 256;
            cp_async16(dst + (u32)u * 16, src + (size_t)u * 16);
        }
    };

    fill_x(0); fill_B(0); CP_COMMIT();

#pragma unroll 1
    for (int kc = 0; kc < 4; kc++) {
        CP_WAIT0();
        __syncthreads();
        if (kc < 3) { fill_x(kc + 1); fill_B(kc + 1); CP_COMMIT(); }

        // ---- convert fp32 smem -> fp16 swizzled tile + g_xh2 dump ----
        {
            const float* xf = (const float*)(smem + ((kc & 1) ? XF1_OFF : XF0_OFF));
            u32 hp[16];
#pragma unroll
            for (int u = 0; u < 16; u++) {
                float f0 = xf[(ckh * 32 + 2 * u) * 128 + cm];
                float f1 = xf[(ckh * 32 + 2 * u + 1) * 128 + cm];
                __half2 h2 = __floats2half2_rn(f0, f1);
                memcpy(&hp[u], &h2, 4);
            }
#pragma unroll
            for (int j = 0; j < 4; j++) {
                u32 off = ((u32)(ckh * 64 + j * 16)) ^ cxm;
                uint4 v4 = make_uint4(hp[4 * j], hp[4 * j + 1],
                                      hp[4 * j + 2], hp[4 * j + 3]);
                *(uint4*)(smem + XH_OFF + cm * 128 + off) = v4;
            }
            u32* xo = xh_out + (size_t)(kc * 32 + ckh * 16) * NN;
#pragma unroll
            for (int u = 0; u < 16; u++)
                xo[(size_t)u * NN] = hp[u];
        }
        __syncthreads();

        // ---- compute: 4 k16 steps ----
        const u32 Bbase = sb + (u32)((kc & 1) ? B1_OFF : B0_OFF);
#pragma unroll
        for (int j = 0; j < 4; j++) {
            const u32 ka  = ((u32)(j * 32) + a_ksel) ^ xm;
            const u32 kb2 = ((u32)(j * 32) + b_ksel) ^ xm;
            u32 Ah0[4], Ah1[4];
            ldm4(Ah0, aXh0 + ka); ldm4(Ah1, aXh1 + ka);
#pragma unroll
            for (int p = 0; p < 7; p++) {
                const int tile = nh * 14 + 2 * p + btile;
                const u32 boff = (u32)(tile * 8 + brow) * 128 + kb2;
                u32 Bf[4];
                ldm4(Bf, Bbase + boff);
                mma16816(acc[p][0][0], Ah0, Bf);
                mma16816(acc[p][0][1], Ah1, Bf);
                mma16816(acc[p][1][0], Ah0, Bf + 2);
                mma16816(acc[p][1][1], Ah1, Bf + 2);
            }
        }
    }

    // ---- epilogue: fp16 u stores (tile == tap) ----
    const int mrow = lane >> 2;
    const int q    = lane & 3;
    u32* up = (u32*)g_u3;
#pragma unroll
    for (int p = 0; p < 7; p++)
#pragma unroll
        for (int tt = 0; tt < 2; tt++) {
            const int tile = nh * 14 + 2 * p + tt;
            if (tile >= NTAP) continue;
#pragma unroll
            for (int mi = 0; mi < 2; mi++) {
                const float* cf = acc[p][tt][mi];
                const int m = n0 + mt0 + mi * 16 + mrow;
                const size_t base = ((size_t)(b * NTAP + tile) * NN + m) * 4 + q;
                __half2 h01 = __floats2half2_rn(cf[0], cf[1]);
                __half2 h23 = __floats2half2_rn(cf[2], cf[3]);
                u32 w01, w23;
                memcpy(&w01, &h01, 4); memcpy(&w23, &h23, 4);
                up[base]      = w01;
                up[base + 32] = w23;
            }
        }
}

// ============================================================================
// K2: shift-add taps + bias + sigmoid -> g_selh (fp16)
// ============================================================================
__global__ void __launch_bounds__(256) shiftadd_kernel(const float* __restrict__ bias) {
    const int gi = blockIdx.x * 256 + threadIdx.x;
    const int b = gi >> 14, n = gi & (NN - 1);
    const int d = n >> 10, h = (n >> 5) & 31, w = n & 31;

    float acc[SS];
#pragma unroll
    for (int s = 0; s < SS; s++) acc[s] = bias[s];

    const uint4* ub = (const uint4*)g_u3 + (size_t)b * NTAP * NN;

#pragma unroll
    for (int kd = 0; kd < 3; kd++) {
        const int dd = d + kd - 1;
        if ((unsigned)dd >= (unsigned)DD_) continue;
#pragma unroll
        for (int kh = 0; kh < 3; kh++) {
            const int hh = h + kh - 1;
            if ((unsigned)hh >= (unsigned)HH_) continue;
#pragma unroll
            for (int kw = 0; kw < 3; kw++) {
                const int ww = w + kw - 1;
                if ((unsigned)ww >= (unsigned)WW_) continue;
                const int tap = (kd * 3 + kh) * 3 + kw;
                const int m = dd * PLANE + hh * WW_ + ww;
                uint4 v = ub[(size_t)tap * NN + m];
                __half2 p0, p1, p2, p3;
                memcpy(&p0, &v.x, 4); memcpy(&p1, &v.y, 4);
                memcpy(&p2, &v.z, 4); memcpy(&p3, &v.w, 4);
                float2 f0 = __half22float2(p0), f1 = __half22float2(p1);
                float2 f2 = __half22float2(p2), f3 = __half22float2(p3);
                acc[0] += f0.x; acc[1] += f0.y; acc[2] += f1.x; acc[3] += f1.y;
                acc[4] += f2.x; acc[5] += f2.y; acc[6] += f3.x; acc[7] += f3.y;
            }
        }
    }
#pragma unroll
    for (int s = 0; s < SS; s++)
        g_selh[((size_t)(b * SS + s)) * NN + n] = __float2half_rn(fast_sigmoid(acc[s]));
}

// ============================================================================
// K3: einsum on tensor cores (dynamic smem).
// P[v][b][s][c] = sum_{n in ksplit v} sel[s][n] * x[c][n]
// grid = B*NK = 128 CTAs, block 256 (8 warps x 4 c-tiles each).
// ============================================================================
__global__ void __launch_bounds__(256) einsum_kernel() {
    extern __shared__ __half esm[];
    __half* sx0  = esm;                          // buf0: 256*XST halfs
    __half* ssel0 = esm + E_SEL_BASE;            // buf0: 16*SELST halfs

    const int b = blockIdx.x >> 4;
    const int v = blockIdx.x & (NK - 1);
    const int tid = threadIdx.x, lane = tid & 31, warp = tid >> 5;
    const int kbase = v * (NN / NK);             // 1024 n per split

    // zero sel buffers once (rows 8..15 must stay 0)
    for (int i = tid; i < 2 * E_SEL_HALFS; i += 256)
        ssel0[i] = __float2half(0.0f);

    const u32*    xsrc = g_xh2 + (size_t)b * (CC / 2) * NN + kbase;
    const __half* ssrc = g_selh + (size_t)b * SS * NN + kbase;

    float acc[4][4];
#pragma unroll
    for (int t = 0; t < 4; t++)
#pragma unroll
        for (int i = 0; i < 4; i++) acc[t][i] = 0.0f;

    const u32 sxb  = smem_u32(sx0);
    const u32 selb = smem_u32(ssel0);
    const int a_row  = (lane & 7) + ((lane >> 3) & 1) * 8;
    const u32 a_kblk = (u32)((lane >> 4) & 1) * 8;      // halfs
    const int bl     = lane & 15;
    const int b_row  = bl & 7;
    const u32 b_kblk = (u32)((bl >> 3) & 1) * 8;        // halfs

    uint4 xr[8]; uint4 selr = make_uint4(0, 0, 0, 0);

#define E_PRELOAD(w) do {                                                     \
    _Pragma("unroll")                                                         \
    for (int p = 0; p < 8; p++) {                                             \
        int i_ = tid + p * 256; int row_ = i_ >> 4, q_ = i_ & 15;             \
        xr[p] = *(const uint4*)(xsrc + (size_t)row_ * NN + (w) * KW + q_ * 4);\
    }                                                                         \
    if (tid < 64)                                                             \
        selr = *(const uint4*)(ssrc + (size_t)(tid >> 3) * NN + (w) * KW +    \
                               (tid & 7) * 8);                                \
} while (0)

#define E_STORE(bufi) do {                                                    \
    __half* sxw  = sx0 + (bufi) * E_SX_HALFS;                                 \
    __half* selw = ssel0 + (bufi) * E_SEL_HALFS;                              \
    _Pragma("unroll")                                                         \
    for (int p = 0; p < 8; p++) {                                             \
        int i_ = tid + p * 256; int row_ = i_ >> 4, q_ = i_ & 15;             \
        u32 e01 = __byte_perm(xr[p].x, xr[p].y, 0x5410);                      \
        u32 e23 = __byte_perm(xr[p].z, xr[p].w, 0x5410);                      \
        u32 o01 = __byte_perm(xr[p].x, xr[p].y, 0x7632);                      \
        u32 o23 = __byte_perm(xr[p].z, xr[p].w, 0x7632);                      \
        *(uint2*)&sxw[(2 * row_) * XST + q_ * 4]     = make_uint2(e01, e23);  \
        *(uint2*)&sxw[(2 * row_ + 1) * XST + q_ * 4] = make_uint2(o01, o23);  \
    }                                                                         \
    if (tid < 64)                                                             \
        *(uint4*)&selw[(tid >> 3) * SELST + (tid & 7) * 8] = selr;            \
} while (0)

    E_PRELOAD(0);
#pragma unroll 1
    for (int w = 0; w < (NN / NK) / KW; w++) {
        const int bufi = w & 1;
        E_STORE(bufi);
        __syncthreads();
        if (w < (NN / NK) / KW - 1) E_PRELOAD(w + 1);

        const u32 selbase = selb + (u32)bufi * E_SEL_HALFS * 2;
        const u32 sxbase  = sxb  + (u32)bufi * E_SX_HALFS * 2;
#pragma unroll
        for (int ks = 0; ks < KW / 16; ks++) {
            u32 A[4];
            ldm4(A, selbase + (u32)a_row * (SELST * 2) +
                    ((u32)(ks * 16) + a_kblk) * 2);
#pragma unroll
            for (int t = 0; t < 4; t++) {
                const int ct = warp * 4 + t;
                u32 Bv[2];
                ldm2(Bv, sxbase + (u32)(ct * 8 + b_row) * (XST * 2) +
                         ((u32)(ks * 16) + b_kblk) * 2);
                mma16816(acc[t], A, Bv);
            }
        }
        __syncthreads();
    }

    // epilogue: rows 0..7 = s
    const int s = lane >> 2;
#pragma unroll
    for (int t = 0; t < 4; t++) {
        const int c = (warp * 4 + t) * 8 + (lane & 3) * 2;
        float* dst = &g_partial[(((size_t)v * BB + b) * SS + s) * CC + c];
        dst[0] = acc[t][0];
        dst[1] = acc[t][1];
    }
#undef E_PRELOAD
#undef E_STORE
}

// ============================================================================
// K4: out[i] = sum_v partial[v][i] / N
// ============================================================================
__global__ void __launch_bounds__(256) reduce_kernel(float* __restrict__ out) {
    int i = blockIdx.x * 256 + threadIdx.x;
    if (i < BB * SS * CC) {
        float s = 0.f;
#pragma unroll
        for (int v = 0; v < NK; v++)
            s += g_partial[(size_t)v * (BB * SS * CC) + i];
        out[i] = s * (1.0f / (float)NN);
    }
}

// ============================================================================
extern "C" void kernel_launch(void* const* d_in, const int* in_sizes, int n_in,
                              void* d_out, int out_size) {
    const float* x    = (const float*)d_in[0];   // [8,256,16,32,32]
    const float* Wc   = (const float*)d_in[1];   // [8,256,3,3,3]
    const float* bias = (const float*)d_in[2];   // [8]
    float* out = (float*)d_out;                  // [8,8,256]

    cudaFuncSetAttribute(gemm_kernel,
                         cudaFuncAttributeMaxDynamicSharedMemorySize, GEMM_SMEM);
    cudaFuncSetAttribute(einsum_kernel,
                         cudaFuncAttributeMaxDynamicSharedMemorySize, EINSUM_SMEM);

    prep_kernel<<<BROWS, 256>>>(Wc);
    gemm_kernel<<<BB * (NN / 128), 256, GEMM_SMEM>>>(x);
    shiftadd_kernel<<<(BB * NN) / 256, 256>>>(bias);
    einsum_kernel<<<BB * NK, 256, EINSUM_SMEM>>>();
    reduce_kernel<<<(BB * SS * CC + 255) / 256, 256>>>(out);
}